// round 4
// baseline (speedup 1.0000x reference)
#include <cuda_runtime.h>
#include <cuda_bf16.h>
#include <cuda_fp8.h>
#include <cstdint>
#include <cstddef>

// Problem shape (fixed by the dataset)
#define BATCH  2
#define SEQ    2048
#define DMODEL 2048
#define NHEAD  16
#define HDIM   128
#define MROWS  (BATCH*SEQ)   // 4096
#define NACT   (MROWS*DMODEL)    // 8388608
#define NWEI   (DMODEL*DMODEL)   // 4194304

// ---------------- scratch: __device__ globals (no dynamic allocation) ----------
__device__ __nv_bfloat16 g_Xq [NACT];
__device__ __nv_bfloat16 g_Xkv[NACT];
__device__ __nv_bfloat16 g_Wq [NWEI];
__device__ __nv_bfloat16 g_Wk [NWEI];
__device__ __nv_bfloat16 g_Wv [NWEI];
__device__ __nv_bfloat16 g_Wo [NWEI];
__device__ __nv_bfloat16 g_Q  [NACT];
__device__ __nv_bfloat16 g_K  [NACT];
__device__ __nv_bfloat16 g_V  [NACT];
__device__ __nv_bfloat16 g_AO [NACT];
__device__ float g_m[BATCH*NHEAD*SEQ];
__device__ float g_l[BATCH*NHEAD*SEQ];

// ---------------- fp8 helpers ----------------
// round float -> e4m3 -> back to float (exactly representable in bf16/f32)
__device__ __forceinline__ float fp8_round(float x) {
    __nv_fp8_storage_t r = __nv_cvt_float_to_fp8(x, __NV_SATFINITE, __NV_E4M3);
    __half_raw hr = __nv_cvt_fp8_to_halfraw(r, __NV_E4M3);
    return __half2float(__half(hr));
}
// reference does fp32 -> bf16 -> e4m3; bf16 step is exact in f32, so chain them
__device__ __forceinline__ float fp8_round_bf(float x) {
    float xb = __bfloat162float(__float2bfloat16(x));
    return fp8_round(xb);
}

// ---------------- quantize kernels ----------------
__global__ void k_quant_f32(const float* __restrict__ in, __nv_bfloat16* __restrict__ out, int n) {
    int i = blockIdx.x * blockDim.x + threadIdx.x;
    if (i < n) out[i] = __float2bfloat16(fp8_round(in[i]));
}
__global__ void k_quant_bf_inplace(__nv_bfloat16* buf, int n) {
    int i = blockIdx.x * blockDim.x + threadIdx.x;
    if (i < n) buf[i] = __float2bfloat16(fp8_round(__bfloat162float(buf[i])));
}

// ---------------- tiled GEMM: bf16 x bf16 -> fp32 accum ----------------
// C[M,N] = A[M,K] * B[K,N], row-major. Output either bf16 (intermediates)
// or fp32 (final result buffer; value is still bf16-rounded first, matching
// the reference's preferred_element_type=BF16, then widened to f32).
#define GBM 128
#define GBN 128
#define GBK 16
template <bool F32OUT>
__global__ __launch_bounds__(256) void k_gemm(const __nv_bfloat16* __restrict__ A,
                                              const __nv_bfloat16* __restrict__ Bm,
                                              void* __restrict__ Cout,
                                              int M, int N, int K)
{
    __shared__ float As[GBK][GBM + 4];   // stored transposed, padded
    __shared__ float Bs[GBK][GBN];
    const int tid = threadIdx.x;
    const int tx = tid & 15, ty = tid >> 4;
    const int row0 = blockIdx.y * GBM;
    const int col0 = blockIdx.x * GBN;
    const int ar = tid >> 1;            // 0..127
    const int ac = (tid & 1) * 8;       // 0 or 8
    const int br = tid >> 4;            // 0..15
    const int bc = (tid & 15) * 8;      // 0..120
    float acc[8][8] = {};
    for (int kk = 0; kk < K; kk += GBK) {
        uint4 av = *reinterpret_cast<const uint4*>(A + (size_t)(row0 + ar) * K + kk + ac);
        const __nv_bfloat16* ap = reinterpret_cast<const __nv_bfloat16*>(&av);
        #pragma unroll
        for (int u = 0; u < 8; u++) As[ac + u][ar] = __bfloat162float(ap[u]);
        uint4 bv = *reinterpret_cast<const uint4*>(Bm + (size_t)(kk + br) * N + col0 + bc);
        const __nv_bfloat16* bp = reinterpret_cast<const __nv_bfloat16*>(&bv);
        #pragma unroll
        for (int u = 0; u < 8; u++) Bs[br][bc + u] = __bfloat162float(bp[u]);
        __syncthreads();
        #pragma unroll
        for (int k = 0; k < GBK; k++) {
            float4 a0 = *reinterpret_cast<const float4*>(&As[k][ty * 8]);
            float4 a1 = *reinterpret_cast<const float4*>(&As[k][ty * 8 + 4]);
            float4 b0 = *reinterpret_cast<const float4*>(&Bs[k][tx * 8]);
            float4 b1 = *reinterpret_cast<const float4*>(&Bs[k][tx * 8 + 4]);
            float a[8] = {a0.x, a0.y, a0.z, a0.w, a1.x, a1.y, a1.z, a1.w};
            float b[8] = {b0.x, b0.y, b0.z, b0.w, b1.x, b1.y, b1.z, b1.w};
            #pragma unroll
            for (int i = 0; i < 8; i++)
                #pragma unroll
                for (int j = 0; j < 8; j++) acc[i][j] += a[i] * b[j];
        }
        __syncthreads();
    }
    #pragma unroll
    for (int i = 0; i < 8; i++) {
        size_t r = (size_t)(row0 + ty * 8 + i);
        #pragma unroll
        for (int j = 0; j < 8; j++) {
            __nv_bfloat16 vb = __float2bfloat16(acc[i][j]);
            if (F32OUT) {
                ((float*)Cout)[r * N + col0 + tx * 8 + j] = __bfloat162float(vb);
            } else {
                ((__nv_bfloat16*)Cout)[r * N + col0 + tx * 8 + j] = vb;
            }
        }
    }
}

// ---------------- attention ----------------
#define QTILE 64
#define KTILE 64

// load a 64 x HDIM bf16 tile transposed into dst[HDIM][64]
__device__ __forceinline__ void load_tile_T(const __nv_bfloat16* __restrict__ src, int ldsrc,
                                            __nv_bfloat16 (*dst)[QTILE], int tid)
{
    for (int vv = tid; vv < QTILE * HDIM / 8; vv += 256) {
        int r = vv >> 4;          // token 0..63
        int c = (vv & 15) * 8;    // headdim element
        uint4 u = *reinterpret_cast<const uint4*>(src + (size_t)r * ldsrc + c);
        const __nv_bfloat16* p = reinterpret_cast<const __nv_bfloat16*>(&u);
        #pragma unroll
        for (int t = 0; t < 8; t++) dst[c + t][r] = p[t];
    }
}

// compute 4x4 S micro-tile for (ty,tx) over one 64x64 chunk; applies the
// reference's bf16-round then bf16-scale rounding.
__device__ __forceinline__ void attn_s_chunk(const __nv_bfloat16 (*Qt)[QTILE],
                                             const __nv_bfloat16 (*Kt)[KTILE],
                                             int ty, int tx, float scale_b, float s[4][4])
{
    #pragma unroll
    for (int i = 0; i < 4; i++)
        #pragma unroll
        for (int j = 0; j < 4; j++) s[i][j] = 0.f;
    #pragma unroll 4
    for (int e = 0; e < HDIM; e++) {
        uint2 au = *reinterpret_cast<const uint2*>(&Qt[e][ty * 4]);
        uint2 bu = *reinterpret_cast<const uint2*>(&Kt[e][tx * 4]);
        const __nv_bfloat16* ap = reinterpret_cast<const __nv_bfloat16*>(&au);
        const __nv_bfloat16* bp = reinterpret_cast<const __nv_bfloat16*>(&bu);
        float a[4], b[4];
        #pragma unroll
        for (int i = 0; i < 4; i++) a[i] = __bfloat162float(ap[i]);
        #pragma unroll
        for (int j = 0; j < 4; j++) b[j] = __bfloat162float(bp[j]);
        #pragma unroll
        for (int i = 0; i < 4; i++)
            #pragma unroll
            for (int j = 0; j < 4; j++) s[i][j] += a[i] * b[j];
    }
    #pragma unroll
    for (int i = 0; i < 4; i++)
        #pragma unroll
        for (int j = 0; j < 4; j++) {
            float t = __bfloat162float(__float2bfloat16(s[i][j]));     // einsum -> bf16
            s[i][j] = __bfloat162float(__float2bfloat16(t * scale_b)); // * scale in bf16
        }
}

// Pass A: per-row max and sum(exp) statistics (streaming, exact)
__global__ __launch_bounds__(256) void k_attn_stats()
{
    __shared__ __nv_bfloat16 Qt[HDIM][QTILE];
    __shared__ __nv_bfloat16 Kt[HDIM][KTILE];
    const int tid = threadIdx.x;
    const int tx = tid & 15, ty = tid >> 4;
    const int qt = blockIdx.x, bh = blockIdx.y;
    const int b = bh >> 4, h = bh & 15;
    const float scale_b = __bfloat162float(__float2bfloat16(0.08838834764831845f));
    const __nv_bfloat16* Qg = g_Q + ((size_t)(b * SEQ) + qt * QTILE) * DMODEL + h * HDIM;
    const __nv_bfloat16* Kg = g_K + (size_t)(b * SEQ) * DMODEL + h * HDIM;
    load_tile_T(Qg, DMODEL, Qt, tid);
    float m_run[4], l_run[4];
    #pragma unroll
    for (int i = 0; i < 4; i++) { m_run[i] = -3.0e38f; l_run[i] = 0.f; }
    for (int kt = 0; kt < SEQ / KTILE; kt++) {
        __syncthreads();
        load_tile_T(Kg + (size_t)kt * KTILE * DMODEL, DMODEL, Kt, tid);
        __syncthreads();
        float s[4][4];
        attn_s_chunk(Qt, Kt, ty, tx, scale_b, s);
        #pragma unroll
        for (int i = 0; i < 4; i++) {
            float cm = fmaxf(fmaxf(s[i][0], s[i][1]), fmaxf(s[i][2], s[i][3]));
            cm = fmaxf(cm, __shfl_xor_sync(0xffffffffu, cm, 8, 16));
            cm = fmaxf(cm, __shfl_xor_sync(0xffffffffu, cm, 4, 16));
            cm = fmaxf(cm, __shfl_xor_sync(0xffffffffu, cm, 2, 16));
            cm = fmaxf(cm, __shfl_xor_sync(0xffffffffu, cm, 1, 16));
            float mn = fmaxf(m_run[i], cm);
            float ls = expf(s[i][0] - mn) + expf(s[i][1] - mn)
                     + expf(s[i][2] - mn) + expf(s[i][3] - mn);
            ls += __shfl_xor_sync(0xffffffffu, ls, 8, 16);
            ls += __shfl_xor_sync(0xffffffffu, ls, 4, 16);
            ls += __shfl_xor_sync(0xffffffffu, ls, 2, 16);
            ls += __shfl_xor_sync(0xffffffffu, ls, 1, 16);
            l_run[i] = l_run[i] * expf(m_run[i] - mn) + ls;
            m_run[i] = mn;
        }
    }
    if (tx == 0) {
        #pragma unroll
        for (int i = 0; i < 4; i++) {
            int qrow = qt * QTILE + ty * 4 + i;
            g_m[(size_t)bh * SEQ + qrow] = m_run[i];
            g_l[(size_t)bh * SEQ + qrow] = l_run[i];
        }
    }
}

// Pass B: recompute S, P = e4m3(bf16(softmax)), O += P * V (V already e4m3)
__global__ __launch_bounds__(256) void k_attn_av()
{
    __shared__ __nv_bfloat16 Qt[HDIM][QTILE];
    __shared__ __nv_bfloat16 KV[HDIM * KTILE];     // Kt view, then V row-major view
    __shared__ __nv_bfloat16 Ps[QTILE][KTILE];
    const int tid = threadIdx.x;
    const int tx = tid & 15, ty = tid >> 4;
    const int qt = blockIdx.x, bh = blockIdx.y;
    const int b = bh >> 4, h = bh & 15;
    const float scale_b = __bfloat162float(__float2bfloat16(0.08838834764831845f));
    const __nv_bfloat16* Qg = g_Q + ((size_t)(b * SEQ) + qt * QTILE) * DMODEL + h * HDIM;
    const __nv_bfloat16* Kg = g_K + (size_t)(b * SEQ) * DMODEL + h * HDIM;
    const __nv_bfloat16* Vg = g_V + (size_t)(b * SEQ) * DMODEL + h * HDIM;
    load_tile_T(Qg, DMODEL, Qt, tid);
    float mrow[4], lrow[4];
    #pragma unroll
    for (int i = 0; i < 4; i++) {
        int qrow = qt * QTILE + ty * 4 + i;
        mrow[i] = g_m[(size_t)bh * SEQ + qrow];
        lrow[i] = g_l[(size_t)bh * SEQ + qrow];
    }
    float acc[4][8] = {};
    __nv_bfloat16 (*Kt)[KTILE] = reinterpret_cast<__nv_bfloat16(*)[KTILE]>(KV);
    for (int kt = 0; kt < SEQ / KTILE; kt++) {
        __syncthreads();   // protect KV/Ps from previous iteration readers
        load_tile_T(Kg + (size_t)kt * KTILE * DMODEL, DMODEL, Kt, tid);
        __syncthreads();
        float s[4][4];
        attn_s_chunk(Qt, Kt, ty, tx, scale_b, s);
        #pragma unroll
        for (int i = 0; i < 4; i++) {
            #pragma unroll
            for (int j = 0; j < 4; j++) {
                float p = expf(s[i][j] - mrow[i]) / lrow[i];   // fp32 softmax
                Ps[ty * 4 + i][tx * 4 + j] = __float2bfloat16(fp8_round_bf(p));
            }
        }
        __syncthreads();   // all K reads + P writes done; reuse KV for V
        for (int vv = tid; vv < KTILE * HDIM / 8; vv += 256) {
            int r = vv >> 4, c = (vv & 15) * 8;
            *reinterpret_cast<uint4*>(&KV[r * HDIM + c]) =
                *reinterpret_cast<const uint4*>(Vg + (size_t)(kt * KTILE + r) * DMODEL + c);
        }
        __syncthreads();
        #pragma unroll 4
        for (int kk = 0; kk < KTILE; kk++) {
            float p4[4];
            #pragma unroll
            for (int i = 0; i < 4; i++) p4[i] = __bfloat162float(Ps[ty * 4 + i][kk]);
            uint4 vu = *reinterpret_cast<const uint4*>(&KV[kk * HDIM + tx * 8]);
            const __nv_bfloat16* vp = reinterpret_cast<const __nv_bfloat16*>(&vu);
            #pragma unroll
            for (int j = 0; j < 8; j++) {
                float vf = __bfloat162float(vp[j]);
                #pragma unroll
                for (int i = 0; i < 4; i++) acc[i][j] += p4[i] * vf;
            }
        }
    }
    // attn_output: fp32 accum -> bf16 (einsum out), then e4m3 (input to Wo proj)
    #pragma unroll
    for (int i = 0; i < 4; i++) {
        size_t r = (size_t)(b * SEQ + qt * QTILE + ty * 4 + i);
        #pragma unroll
        for (int j = 0; j < 8; j++) {
            g_AO[r * DMODEL + h * HDIM + tx * 8 + j] =
                __float2bfloat16(fp8_round_bf(acc[i][j]));
        }
    }
}

// ---------------- launch ----------------
extern "C" void kernel_launch(void* const* d_in, const int* in_sizes, int n_in,
                              void* d_out, int out_size)
{
    // ---- input-order detection (robust to either convention) --------------
    int iq, ikv, iwq, iwk, iwv, iwo;
    if (in_sizes[0] == NACT) {           // signature / insertion order
        iq = 0; ikv = 1; iwq = 2; iwk = 3; iwv = 4; iwo = 5;
    } else {                             // alphabetically sorted keys
        iwk = 0; iwo = 1; iwq = 2; iwv = 3; ikv = 4; iq = 5;
    }
    const float* in_q  = (const float*)d_in[iq];
    const float* in_kv = (const float*)d_in[ikv];
    const float* wq = (const float*)d_in[iwq];
    const float* wk = (const float*)d_in[iwk];
    const float* wv = (const float*)d_in[iwv];
    const float* wo = (const float*)d_in[iwo];

    __nv_bfloat16 *xq, *xkv, *wqe, *wke, *wve, *woe, *q, *k, *v, *ao;
    cudaGetSymbolAddress((void**)&xq,  g_Xq);
    cudaGetSymbolAddress((void**)&xkv, g_Xkv);
    cudaGetSymbolAddress((void**)&wqe, g_Wq);
    cudaGetSymbolAddress((void**)&wke, g_Wk);
    cudaGetSymbolAddress((void**)&wve, g_Wv);
    cudaGetSymbolAddress((void**)&woe, g_Wo);
    cudaGetSymbolAddress((void**)&q,   g_Q);
    cudaGetSymbolAddress((void**)&k,   g_K);
    cudaGetSymbolAddress((void**)&v,   g_V);
    cudaGetSymbolAddress((void**)&ao,  g_AO);

    // quantize activations + weights to e4m3 (stored exactly as bf16)
    k_quant_f32<<<NACT / 256, 256>>>(in_q,  xq,  NACT);
    k_quant_f32<<<NACT / 256, 256>>>(in_kv, xkv, NACT);
    k_quant_f32<<<NWEI / 256, 256>>>(wq, wqe, NWEI);
    k_quant_f32<<<NWEI / 256, 256>>>(wk, wke, NWEI);
    k_quant_f32<<<NWEI / 256, 256>>>(wv, wve, NWEI);
    k_quant_f32<<<NWEI / 256, 256>>>(wo, woe, NWEI);

    // projections: fp8-emulated GEMMs, fp32 accumulate, bf16 out
    dim3 gg(DMODEL / GBN, MROWS / GBM);
    k_gemm<false><<<gg, 256>>>(xq,  wqe, q, MROWS, DMODEL, DMODEL);
    k_gemm<false><<<gg, 256>>>(xkv, wke, k, MROWS, DMODEL, DMODEL);
    k_gemm<false><<<gg, 256>>>(xkv, wve, v, MROWS, DMODEL, DMODEL);

    // v is cast to e4m3 inside the AV einsum in the reference
    k_quant_bf_inplace<<<NACT / 256, 256>>>(v, NACT);

    // attention: stats pass then PV pass
    dim3 ga(SEQ / QTILE, BATCH * NHEAD);
    k_attn_stats<<<ga, 256>>>();
    k_attn_av<<<ga, 256>>>();

    // output projection: bf16-rounded values, widened to FLOAT32 output buffer
    k_gemm<true><<<gg, 256>>>(ao, woe, d_out, MROWS, DMODEL, DMODEL);
}

// round 7
// speedup vs baseline: 2.8679x; 2.8679x over previous
#include <cuda_runtime.h>
#include <cuda_bf16.h>
#include <cuda_fp8.h>
#include <cstdint>
#include <cstddef>

// Problem shape (fixed by the dataset)
#define BATCH  2
#define SEQ    2048
#define DMODEL 2048
#define NHEAD  16
#define HDIM   128
#define MROWS  (BATCH*SEQ)       // 4096
#define NACT   (MROWS*DMODEL)    // 8388608
#define NWEI   (DMODEL*DMODEL)   // 4194304

// ---------------- scratch: __device__ globals (no dynamic allocation) ----------
__device__ __nv_bfloat16 g_Xq [NACT];
__device__ __nv_bfloat16 g_Xkv[NACT];
__device__ __nv_bfloat16 g_Wq [NWEI];   // TRANSPOSED [n][k], e4m3-rounded bf16
__device__ __nv_bfloat16 g_Wk [NWEI];
__device__ __nv_bfloat16 g_Wv [NWEI];
__device__ __nv_bfloat16 g_Wo [NWEI];
__device__ __nv_bfloat16 g_Q  [NACT];
__device__ __nv_bfloat16 g_K  [NACT];
__device__ __nv_bfloat16 g_V  [NACT];
__device__ __nv_bfloat16 g_AO [NACT];
__device__ float g_m[BATCH*NHEAD*SEQ];
__device__ float g_l[BATCH*NHEAD*SEQ];

// ---------------- small helpers ----------------
__device__ __forceinline__ uint32_t smem_u32(const void* p) {
    uint32_t a;
    asm("{ .reg .u64 t; cvta.to.shared.u64 t, %1; cvt.u32.u64 %0, t; }" : "=r"(a) : "l"(p));
    return a;
}
__device__ __forceinline__ void ldmatrix_x4(uint32_t& r0, uint32_t& r1,
                                            uint32_t& r2, uint32_t& r3, uint32_t addr) {
    asm volatile("ldmatrix.sync.aligned.m8n8.x4.shared.b16 {%0,%1,%2,%3}, [%4];"
                 : "=r"(r0), "=r"(r1), "=r"(r2), "=r"(r3) : "r"(addr));
}
__device__ __forceinline__ void mma16816(float* c, const uint32_t* a, const uint32_t* b) {
    asm volatile(
        "mma.sync.aligned.m16n8k16.row.col.f32.bf16.bf16.f32 "
        "{%0,%1,%2,%3}, {%4,%5,%6,%7}, {%8,%9}, {%0,%1,%2,%3};"
        : "+f"(c[0]), "+f"(c[1]), "+f"(c[2]), "+f"(c[3])
        : "r"(a[0]), "r"(a[1]), "r"(a[2]), "r"(a[3]), "r"(b[0]), "r"(b[1]));
}

// ---------------- fp8 helpers ----------------
__device__ __forceinline__ float fp8_round(float x) {
    __nv_fp8_storage_t r = __nv_cvt_float_to_fp8(x, __NV_SATFINITE, __NV_E4M3);
    __half_raw hr = __nv_cvt_fp8_to_halfraw(r, __NV_E4M3);
    return __half2float(__half(hr));
}
__device__ __forceinline__ float fp8_round_bf(float x) {
    float xb = __bfloat162float(__float2bfloat16(x));
    return fp8_round(xb);
}

// ---------------- quantize / transpose kernels ----------------
__global__ void k_quant_f32(const float* __restrict__ in, __nv_bfloat16* __restrict__ out, int n) {
    int i = blockIdx.x * blockDim.x + threadIdx.x;
    if (i < n) out[i] = __float2bfloat16(fp8_round(in[i]));
}
// Wt[n][k] = e4m3(W[k][n]), bf16 storage (mma .col operand wants B as [N,K])
__global__ __launch_bounds__(1024) void k_wtrans(const float* __restrict__ W,
                                                 __nv_bfloat16* __restrict__ Wt) {
    __shared__ float t[32][33];
    int tx = threadIdx.x & 31, ty = threadIdx.x >> 5;
    int n0 = blockIdx.x * 32, k0 = blockIdx.y * 32;
    t[ty][tx] = W[(size_t)(k0 + ty) * DMODEL + n0 + tx];
    __syncthreads();
    Wt[(size_t)(n0 + ty) * DMODEL + k0 + tx] = __float2bfloat16(fp8_round(t[tx][ty]));
}

// ---------------- mma.sync GEMM ----------------
// C[M,N] = A[M,K] @ Bt[N,K]^T  (bf16 in, fp32 accum)
// epi: 0 = bf16(acc), 1 = bf16(e4m3(bf16(acc))) [V path], 2 = f32(bf16(acc)) [final]
#define TBM 128
#define TBN 128
#define TBK 32
#define SKP 40   // padded row length (bf16 elems): 80B stride, ldmatrix conflict-free
__global__ __launch_bounds__(256) void k_gemm_mma(const __nv_bfloat16* __restrict__ A,
                                                  const __nv_bfloat16* __restrict__ Bt,
                                                  void* __restrict__ C,
                                                  int M, int N, int K, int epi)
{
    __shared__ __nv_bfloat16 As[TBM][SKP];
    __shared__ __nv_bfloat16 Bs[TBN][SKP];
    const int tid = threadIdx.x, wid = tid >> 5, lane = tid & 31;
    const int wm = wid & 3, wn = wid >> 2;          // warp grid 4(M) x 2(N)
    const int row0 = blockIdx.y * TBM, col0 = blockIdx.x * TBN;

    // ldmatrix lane-address selectors (same formula for A and B)
    const int rsel = (lane & 7) + ((lane >> 3) & 1) * 8;   // row within 16-row region
    const int csel = (lane >> 4) * 8;                      // col offset 0 or 8

    // precompute shared addresses (constant across K chunks)
    uint32_t aAddr[2][2], bAddr[2][4];
    #pragma unroll
    for (int ks = 0; ks < 2; ks++) {
        #pragma unroll
        for (int mt = 0; mt < 2; mt++)
            aAddr[ks][mt] = smem_u32(&As[wm * 32 + mt * 16 + rsel][ks * 16 + csel]);
        #pragma unroll
        for (int nt = 0; nt < 4; nt++)
            bAddr[ks][nt] = smem_u32(&Bs[wn * 64 + nt * 16 + rsel][ks * 16 + csel]);
    }

    float acc[2][8][4] = {};

    for (int kk = 0; kk < K; kk += TBK) {
        __syncthreads();
        // load A/B tiles: 128x32 bf16 each = 512 uint4; 256 threads x 2
        #pragma unroll
        for (int it = 0; it < 2; it++) {
            int idx = tid + it * 256;
            int r = idx >> 2, cg = (idx & 3) * 8;
            *reinterpret_cast<uint4*>(&As[r][cg]) =
                *reinterpret_cast<const uint4*>(A + (size_t)(row0 + r) * K + kk + cg);
            *reinterpret_cast<uint4*>(&Bs[r][cg]) =
                *reinterpret_cast<const uint4*>(Bt + (size_t)(col0 + r) * K + kk + cg);
        }
        __syncthreads();
        #pragma unroll
        for (int ks = 0; ks < 2; ks++) {
            uint32_t a[2][4];
            #pragma unroll
            for (int mt = 0; mt < 2; mt++)
                ldmatrix_x4(a[mt][0], a[mt][1], a[mt][2], a[mt][3], aAddr[ks][mt]);
            uint32_t bf[8][2];
            #pragma unroll
            for (int nt = 0; nt < 4; nt++) {
                uint32_t r0, r1, r2, r3;
                ldmatrix_x4(r0, r1, r2, r3, bAddr[ks][nt]);
                bf[nt * 2 + 0][0] = r0; bf[nt * 2 + 0][1] = r2;
                bf[nt * 2 + 1][0] = r1; bf[nt * 2 + 1][1] = r3;
            }
            #pragma unroll
            for (int mt = 0; mt < 2; mt++)
                #pragma unroll
                for (int ng = 0; ng < 8; ng++)
                    mma16816(acc[mt][ng], a[mt], bf[ng]);
        }
    }

    // epilogue: thread holds rows quad, quad+8; cols qt*2, qt*2+1 per m16n8 tile
    const int quad = lane >> 2, qt = lane & 3;
    #pragma unroll
    for (int mt = 0; mt < 2; mt++) {
        #pragma unroll
        for (int ng = 0; ng < 8; ng++) {
            int r0 = row0 + wm * 32 + mt * 16 + quad;
            int c  = col0 + wn * 64 + ng * 8 + qt * 2;
            #pragma unroll
            for (int h = 0; h < 2; h++) {       // half: rows quad / quad+8
                size_t r = (size_t)(r0 + h * 8);
                float v0 = acc[mt][ng][h * 2 + 0];
                float v1 = acc[mt][ng][h * 2 + 1];
                if (epi == 2) {
                    float2 o;
                    o.x = __bfloat162float(__float2bfloat16(v0));
                    o.y = __bfloat162float(__float2bfloat16(v1));
                    *reinterpret_cast<float2*>((float*)C + r * N + c) = o;
                } else {
                    __nv_bfloat16 b0 = __float2bfloat16(v0);
                    __nv_bfloat16 b1 = __float2bfloat16(v1);
                    if (epi == 1) {
                        b0 = __float2bfloat16(fp8_round(__bfloat162float(b0)));
                        b1 = __float2bfloat16(fp8_round(__bfloat162float(b1)));
                    }
                    __nv_bfloat162 o = __halves2bfloat162(b0, b1);
                    *reinterpret_cast<__nv_bfloat162*>((__nv_bfloat16*)C + r * N + c) = o;
                }
            }
        }
    }
}

// ---------------- attention (unchanged from passing round) ----------------
#define QTILE 64
#define KTILE 64

__device__ __forceinline__ void load_tile_T(const __nv_bfloat16* __restrict__ src, int ldsrc,
                                            __nv_bfloat16 (*dst)[QTILE], int tid)
{
    for (int vv = tid; vv < QTILE * HDIM / 8; vv += 256) {
        int r = vv >> 4;
        int c = (vv & 15) * 8;
        uint4 u = *reinterpret_cast<const uint4*>(src + (size_t)r * ldsrc + c);
        const __nv_bfloat16* p = reinterpret_cast<const __nv_bfloat16*>(&u);
        #pragma unroll
        for (int t = 0; t < 8; t++) dst[c + t][r] = p[t];
    }
}

__device__ __forceinline__ void attn_s_chunk(const __nv_bfloat16 (*Qt)[QTILE],
                                             const __nv_bfloat16 (*Kt)[KTILE],
                                             int ty, int tx, float scale_b, float s[4][4])
{
    #pragma unroll
    for (int i = 0; i < 4; i++)
        #pragma unroll
        for (int j = 0; j < 4; j++) s[i][j] = 0.f;
    #pragma unroll 4
    for (int e = 0; e < HDIM; e++) {
        uint2 au = *reinterpret_cast<const uint2*>(&Qt[e][ty * 4]);
        uint2 bu = *reinterpret_cast<const uint2*>(&Kt[e][tx * 4]);
        const __nv_bfloat16* ap = reinterpret_cast<const __nv_bfloat16*>(&au);
        const __nv_bfloat16* bp = reinterpret_cast<const __nv_bfloat16*>(&bu);
        float a[4], b[4];
        #pragma unroll
        for (int i = 0; i < 4; i++) a[i] = __bfloat162float(ap[i]);
        #pragma unroll
        for (int j = 0; j < 4; j++) b[j] = __bfloat162float(bp[j]);
        #pragma unroll
        for (int i = 0; i < 4; i++)
            #pragma unroll
            for (int j = 0; j < 4; j++) s[i][j] += a[i] * b[j];
    }
    #pragma unroll
    for (int i = 0; i < 4; i++)
        #pragma unroll
        for (int j = 0; j < 4; j++) {
            float t = __bfloat162float(__float2bfloat16(s[i][j]));
            s[i][j] = __bfloat162float(__float2bfloat16(t * scale_b));
        }
}

__global__ __launch_bounds__(256) void k_attn_stats()
{
    __shared__ __nv_bfloat16 Qt[HDIM][QTILE];
    __shared__ __nv_bfloat16 Kt[HDIM][KTILE];
    const int tid = threadIdx.x;
    const int tx = tid & 15, ty = tid >> 4;
    const int qt = blockIdx.x, bh = blockIdx.y;
    const int b = bh >> 4, h = bh & 15;
    const float scale_b = __bfloat162float(__float2bfloat16(0.08838834764831845f));
    const __nv_bfloat16* Qg = g_Q + ((size_t)(b * SEQ) + qt * QTILE) * DMODEL + h * HDIM;
    const __nv_bfloat16* Kg = g_K + (size_t)(b * SEQ) * DMODEL + h * HDIM;
    load_tile_T(Qg, DMODEL, Qt, tid);
    float m_run[4], l_run[4];
    #pragma unroll
    for (int i = 0; i < 4; i++) { m_run[i] = -3.0e38f; l_run[i] = 0.f; }
    for (int kt = 0; kt < SEQ / KTILE; kt++) {
        __syncthreads();
        load_tile_T(Kg + (size_t)kt * KTILE * DMODEL, DMODEL, Kt, tid);
        __syncthreads();
        float s[4][4];
        attn_s_chunk(Qt, Kt, ty, tx, scale_b, s);
        #pragma unroll
        for (int i = 0; i < 4; i++) {
            float cm = fmaxf(fmaxf(s[i][0], s[i][1]), fmaxf(s[i][2], s[i][3]));
            cm = fmaxf(cm, __shfl_xor_sync(0xffffffffu, cm, 8, 16));
            cm = fmaxf(cm, __shfl_xor_sync(0xffffffffu, cm, 4, 16));
            cm = fmaxf(cm, __shfl_xor_sync(0xffffffffu, cm, 2, 16));
            cm = fmaxf(cm, __shfl_xor_sync(0xffffffffu, cm, 1, 16));
            float mn = fmaxf(m_run[i], cm);
            float ls = expf(s[i][0] - mn) + expf(s[i][1] - mn)
                     + expf(s[i][2] - mn) + expf(s[i][3] - mn);
            ls += __shfl_xor_sync(0xffffffffu, ls, 8, 16);
            ls += __shfl_xor_sync(0xffffffffu, ls, 4, 16);
            ls += __shfl_xor_sync(0xffffffffu, ls, 2, 16);
            ls += __shfl_xor_sync(0xffffffffu, ls, 1, 16);
            l_run[i] = l_run[i] * expf(m_run[i] - mn) + ls;
            m_run[i] = mn;
        }
    }
    if (tx == 0) {
        #pragma unroll
        for (int i = 0; i < 4; i++) {
            int qrow = qt * QTILE + ty * 4 + i;
            g_m[(size_t)bh * SEQ + qrow] = m_run[i];
            g_l[(size_t)bh * SEQ + qrow] = l_run[i];
        }
    }
}

__global__ __launch_bounds__(256) void k_attn_av()
{
    __shared__ __nv_bfloat16 Qt[HDIM][QTILE];
    __shared__ __nv_bfloat16 KV[HDIM * KTILE];
    __shared__ __nv_bfloat16 Ps[QTILE][KTILE];
    const int tid = threadIdx.x;
    const int tx = tid & 15, ty = tid >> 4;
    const int qt = blockIdx.x, bh = blockIdx.y;
    const int b = bh >> 4, h = bh & 15;
    const float scale_b = __bfloat162float(__float2bfloat16(0.08838834764831845f));
    const __nv_bfloat16* Qg = g_Q + ((size_t)(b * SEQ) + qt * QTILE) * DMODEL + h * HDIM;
    const __nv_bfloat16* Kg = g_K + (size_t)(b * SEQ) * DMODEL + h * HDIM;
    const __nv_bfloat16* Vg = g_V + (size_t)(b * SEQ) * DMODEL + h * HDIM;
    load_tile_T(Qg, DMODEL, Qt, tid);
    float mrow[4], lrow[4];
    #pragma unroll
    for (int i = 0; i < 4; i++) {
        int qrow = qt * QTILE + ty * 4 + i;
        mrow[i] = g_m[(size_t)bh * SEQ + qrow];
        lrow[i] = g_l[(size_t)bh * SEQ + qrow];
    }
    float acc[4][8] = {};
    __nv_bfloat16 (*Kt)[KTILE] = reinterpret_cast<__nv_bfloat16(*)[KTILE]>(KV);
    for (int kt = 0; kt < SEQ / KTILE; kt++) {
        __syncthreads();
        load_tile_T(Kg + (size_t)kt * KTILE * DMODEL, DMODEL, Kt, tid);
        __syncthreads();
        float s[4][4];
        attn_s_chunk(Qt, Kt, ty, tx, scale_b, s);
        #pragma unroll
        for (int i = 0; i < 4; i++) {
            #pragma unroll
            for (int j = 0; j < 4; j++) {
                float p = expf(s[i][j] - mrow[i]) / lrow[i];
                Ps[ty * 4 + i][tx * 4 + j] = __float2bfloat16(fp8_round_bf(p));
            }
        }
        __syncthreads();
        for (int vv = tid; vv < KTILE * HDIM / 8; vv += 256) {
            int r = vv >> 4, c = (vv & 15) * 8;
            *reinterpret_cast<uint4*>(&KV[r * HDIM + c]) =
                *reinterpret_cast<const uint4*>(Vg + (size_t)(kt * KTILE + r) * DMODEL + c);
        }
        __syncthreads();
        #pragma unroll 4
        for (int kk = 0; kk < KTILE; kk++) {
            float p4[4];
            #pragma unroll
            for (int i = 0; i < 4; i++) p4[i] = __bfloat162float(Ps[ty * 4 + i][kk]);
            uint4 vu = *reinterpret_cast<const uint4*>(&KV[kk * HDIM + tx * 8]);
            const __nv_bfloat16* vp = reinterpret_cast<const __nv_bfloat16*>(&vu);
            #pragma unroll
            for (int j = 0; j < 8; j++) {
                float vf = __bfloat162float(vp[j]);
                #pragma unroll
                for (int i = 0; i < 4; i++) acc[i][j] += p4[i] * vf;
            }
        }
    }
    #pragma unroll
    for (int i = 0; i < 4; i++) {
        size_t r = (size_t)(b * SEQ + qt * QTILE + ty * 4 + i);
        #pragma unroll
        for (int j = 0; j < 8; j++) {
            g_AO[r * DMODEL + h * HDIM + tx * 8 + j] =
                __float2bfloat16(fp8_round_bf(acc[i][j]));
        }
    }
}

// ---------------- launch ----------------
extern "C" void kernel_launch(void* const* d_in, const int* in_sizes, int n_in,
                              void* d_out, int out_size)
{
    int iq, ikv, iwq, iwk, iwv, iwo;
    if (in_sizes[0] == NACT) {           // signature / insertion order
        iq = 0; ikv = 1; iwq = 2; iwk = 3; iwv = 4; iwo = 5;
    } else {                             // alphabetically sorted keys
        iwk = 0; iwo = 1; iwq = 2; iwv = 3; ikv = 4; iq = 5;
    }
    const float* in_q  = (const float*)d_in[iq];
    const float* in_kv = (const float*)d_in[ikv];
    const float* wq = (const float*)d_in[iwq];
    const float* wk = (const float*)d_in[iwk];
    const float* wv = (const float*)d_in[iwv];
    const float* wo = (const float*)d_in[iwo];

    __nv_bfloat16 *xq, *xkv, *wqe, *wke, *wve, *woe, *q, *k, *v, *ao;
    cudaGetSymbolAddress((void**)&xq,  g_Xq);
    cudaGetSymbolAddress((void**)&xkv, g_Xkv);
    cudaGetSymbolAddress((void**)&wqe, g_Wq);
    cudaGetSymbolAddress((void**)&wke, g_Wk);
    cudaGetSymbolAddress((void**)&wve, g_Wv);
    cudaGetSymbolAddress((void**)&woe, g_Wo);
    cudaGetSymbolAddress((void**)&q,   g_Q);
    cudaGetSymbolAddress((void**)&k,   g_K);
    cudaGetSymbolAddress((void**)&v,   g_V);
    cudaGetSymbolAddress((void**)&ao,  g_AO);

    // quantize activations; transpose+quantize weights (mma B operand is [N,K])
    k_quant_f32<<<NACT / 256, 256>>>(in_q,  xq,  NACT);
    k_quant_f32<<<NACT / 256, 256>>>(in_kv, xkv, NACT);
    dim3 gt(DMODEL / 32, DMODEL / 32);
    k_wtrans<<<gt, 1024>>>(wq, wqe);
    k_wtrans<<<gt, 1024>>>(wk, wke);
    k_wtrans<<<gt, 1024>>>(wv, wve);
    k_wtrans<<<gt, 1024>>>(wo, woe);

    // projections on mma.sync tensor cores (V fuses e4m3 re-quant into epilogue)
    dim3 gg(DMODEL / TBN, MROWS / TBM);
    k_gemm_mma<<<gg, 256>>>(xq,  wqe, q, MROWS, DMODEL, DMODEL, 0);
    k_gemm_mma<<<gg, 256>>>(xkv, wke, k, MROWS, DMODEL, DMODEL, 0);
    k_gemm_mma<<<gg, 256>>>(xkv, wve, v, MROWS, DMODEL, DMODEL, 1);

    // attention: stats pass then PV pass (scalar, unchanged)
    dim3 ga(SEQ / QTILE, BATCH * NHEAD);
    k_attn_stats<<<ga, 256>>>();
    k_attn_av<<<ga, 256>>>();

    // output projection: bf16-rounded values widened to FLOAT32 output buffer
    k_gemm_mma<<<gg, 256>>>(ao, woe, d_out, MROWS, DMODEL, DMODEL, 2);
}

// round 10
// speedup vs baseline: 9.7646x; 3.4048x over previous
#include <cuda_runtime.h>
#include <cuda_bf16.h>
#include <cuda_fp8.h>
#include <cstdint>
#include <cstddef>

// Problem shape (fixed by the dataset)
#define BATCH  2
#define SEQ    2048
#define DMODEL 2048
#define NHEAD  16
#define HDIM   128
#define MROWS  (BATCH*SEQ)       // 4096
#define NACT   (MROWS*DMODEL)    // 8388608
#define NWEI   (DMODEL*DMODEL)   // 4194304

// ---------------- scratch: __device__ globals (no dynamic allocation) ----------
__device__ __nv_bfloat16 g_Xq [NACT];
__device__ __nv_bfloat16 g_Xkv[NACT];
__device__ __nv_bfloat16 g_Wq [NWEI];   // TRANSPOSED [n][k], e4m3-rounded bf16
__device__ __nv_bfloat16 g_Wk [NWEI];
__device__ __nv_bfloat16 g_Wv [NWEI];
__device__ __nv_bfloat16 g_Wo [NWEI];
__device__ __nv_bfloat16 g_Q  [NACT];
__device__ __nv_bfloat16 g_K  [NACT];
__device__ __nv_bfloat16 g_V  [NACT];
__device__ __nv_bfloat16 g_AO [NACT];
__device__ float g_m[BATCH*NHEAD*SEQ];
__device__ float g_l[BATCH*NHEAD*SEQ];

// ---------------- small helpers ----------------
__device__ __forceinline__ uint32_t smem_u32(const void* p) {
    uint32_t a;
    asm("{ .reg .u64 t; cvta.to.shared.u64 t, %1; cvt.u32.u64 %0, t; }" : "=r"(a) : "l"(p));
    return a;
}
__device__ __forceinline__ void ldmatrix_x4(uint32_t& r0, uint32_t& r1,
                                            uint32_t& r2, uint32_t& r3, uint32_t addr) {
    asm volatile("ldmatrix.sync.aligned.m8n8.x4.shared.b16 {%0,%1,%2,%3}, [%4];"
                 : "=r"(r0), "=r"(r1), "=r"(r2), "=r"(r3) : "r"(addr));
}
__device__ __forceinline__ void ldmatrix_x4_trans(uint32_t& r0, uint32_t& r1,
                                                  uint32_t& r2, uint32_t& r3, uint32_t addr) {
    asm volatile("ldmatrix.sync.aligned.m8n8.x4.trans.shared.b16 {%0,%1,%2,%3}, [%4];"
                 : "=r"(r0), "=r"(r1), "=r"(r2), "=r"(r3) : "r"(addr));
}
__device__ __forceinline__ void mma16816(float* c, const uint32_t* a, const uint32_t* b) {
    asm volatile(
        "mma.sync.aligned.m16n8k16.row.col.f32.bf16.bf16.f32 "
        "{%0,%1,%2,%3}, {%4,%5,%6,%7}, {%8,%9}, {%0,%1,%2,%3};"
        : "+f"(c[0]), "+f"(c[1]), "+f"(c[2]), "+f"(c[3])
        : "r"(a[0]), "r"(a[1]), "r"(a[2]), "r"(a[3]), "r"(b[0]), "r"(b[1]));
}

// ---------------- fp8 helpers ----------------
__device__ __forceinline__ float fp8_round(float x) {
    __nv_fp8_storage_t r = __nv_cvt_float_to_fp8(x, __NV_SATFINITE, __NV_E4M3);
    __half_raw hr = __nv_cvt_fp8_to_halfraw(r, __NV_E4M3);
    return __half2float(__half(hr));
}
__device__ __forceinline__ float fp8_round_bf(float x) {
    float xb = __bfloat162float(__float2bfloat16(x));
    return fp8_round(xb);
}

// ---------------- quantize / transpose kernels ----------------
__global__ void k_quant_f32(const float* __restrict__ in, __nv_bfloat16* __restrict__ out, int n) {
    int i = blockIdx.x * blockDim.x + threadIdx.x;
    if (i < n) out[i] = __float2bfloat16(fp8_round(in[i]));
}
__global__ __launch_bounds__(1024) void k_wtrans(const float* __restrict__ W,
                                                 __nv_bfloat16* __restrict__ Wt) {
    __shared__ float t[32][33];
    int tx = threadIdx.x & 31, ty = threadIdx.x >> 5;
    int n0 = blockIdx.x * 32, k0 = blockIdx.y * 32;
    t[ty][tx] = W[(size_t)(k0 + ty) * DMODEL + n0 + tx];
    __syncthreads();
    Wt[(size_t)(n0 + ty) * DMODEL + k0 + tx] = __float2bfloat16(fp8_round(t[tx][ty]));
}

// ---------------- mma.sync dense GEMM (validated) ----------------
#define TBM 128
#define TBN 128
#define TBK 32
#define SKP 40
__global__ __launch_bounds__(256) void k_gemm_mma(const __nv_bfloat16* __restrict__ A,
                                                  const __nv_bfloat16* __restrict__ Bt,
                                                  void* __restrict__ C,
                                                  int M, int N, int K, int epi)
{
    __shared__ __nv_bfloat16 As[TBM][SKP];
    __shared__ __nv_bfloat16 Bs[TBN][SKP];
    const int tid = threadIdx.x, wid = tid >> 5, lane = tid & 31;
    const int wm = wid & 3, wn = wid >> 2;
    const int row0 = blockIdx.y * TBM, col0 = blockIdx.x * TBN;
    const int rsel = (lane & 7) + ((lane >> 3) & 1) * 8;
    const int csel = (lane >> 4) * 8;

    uint32_t aAddr[2][2], bAddr[2][4];
    #pragma unroll
    for (int ks = 0; ks < 2; ks++) {
        #pragma unroll
        for (int mt = 0; mt < 2; mt++)
            aAddr[ks][mt] = smem_u32(&As[wm * 32 + mt * 16 + rsel][ks * 16 + csel]);
        #pragma unroll
        for (int nt = 0; nt < 4; nt++)
            bAddr[ks][nt] = smem_u32(&Bs[wn * 64 + nt * 16 + rsel][ks * 16 + csel]);
    }

    float acc[2][8][4] = {};

    for (int kk = 0; kk < K; kk += TBK) {
        __syncthreads();
        #pragma unroll
        for (int it = 0; it < 2; it++) {
            int idx = tid + it * 256;
            int r = idx >> 2, cg = (idx & 3) * 8;
            *reinterpret_cast<uint4*>(&As[r][cg]) =
                *reinterpret_cast<const uint4*>(A + (size_t)(row0 + r) * K + kk + cg);
            *reinterpret_cast<uint4*>(&Bs[r][cg]) =
                *reinterpret_cast<const uint4*>(Bt + (size_t)(col0 + r) * K + kk + cg);
        }
        __syncthreads();
        #pragma unroll
        for (int ks = 0; ks < 2; ks++) {
            uint32_t a[2][4];
            #pragma unroll
            for (int mt = 0; mt < 2; mt++)
                ldmatrix_x4(a[mt][0], a[mt][1], a[mt][2], a[mt][3], aAddr[ks][mt]);
            uint32_t bf[8][2];
            #pragma unroll
            for (int nt = 0; nt < 4; nt++) {
                uint32_t r0, r1, r2, r3;
                ldmatrix_x4(r0, r1, r2, r3, bAddr[ks][nt]);
                bf[nt * 2 + 0][0] = r0; bf[nt * 2 + 0][1] = r2;
                bf[nt * 2 + 1][0] = r1; bf[nt * 2 + 1][1] = r3;
            }
            #pragma unroll
            for (int mt = 0; mt < 2; mt++)
                #pragma unroll
                for (int ng = 0; ng < 8; ng++)
                    mma16816(acc[mt][ng], a[mt], bf[ng]);
        }
    }

    const int quad = lane >> 2, qt = lane & 3;
    #pragma unroll
    for (int mt = 0; mt < 2; mt++) {
        #pragma unroll
        for (int ng = 0; ng < 8; ng++) {
            int r0 = row0 + wm * 32 + mt * 16 + quad;
            int c  = col0 + wn * 64 + ng * 8 + qt * 2;
            #pragma unroll
            for (int h = 0; h < 2; h++) {
                size_t r = (size_t)(r0 + h * 8);
                float v0 = acc[mt][ng][h * 2 + 0];
                float v1 = acc[mt][ng][h * 2 + 1];
                if (epi == 2) {
                    float2 o;
                    o.x = __bfloat162float(__float2bfloat16(v0));
                    o.y = __bfloat162float(__float2bfloat16(v1));
                    *reinterpret_cast<float2*>((float*)C + r * N + c) = o;
                } else {
                    __nv_bfloat16 b0 = __float2bfloat16(v0);
                    __nv_bfloat16 b1 = __float2bfloat16(v1);
                    if (epi == 1) {
                        b0 = __float2bfloat16(fp8_round(__bfloat162float(b0)));
                        b1 = __float2bfloat16(fp8_round(__bfloat162float(b1)));
                    }
                    __nv_bfloat162 o = __halves2bfloat162(b0, b1);
                    *reinterpret_cast<__nv_bfloat162*>((__nv_bfloat16*)C + r * N + c) = o;
                }
            }
        }
    }
}

// ================= attention on mma.sync =================
// CTA = 128 q-rows x one (batch,head). 8 warps: 4(M) x 2(N), warp tile 32x64.
// K-chunks of 128 tokens. SMEM row stride 136 bf16 (272B: ldmatrix conflict-free).
#define SKA 136
#define AQ_BYTES  (128*SKA*2)   // 34816

// copy 128x128 bf16 tile (row stride DMODEL) into smem [128][SKA]
// 128*128 bf16 = 2048 uint4 -> 8 iterations of 256 threads (FIXED: was 4 iters
// covering only columns 0..63, leaving half the tile uninitialized -> NaN)
__device__ __forceinline__ void tile_copy(__nv_bfloat16* dst, const __nv_bfloat16* src, int tid) {
    #pragma unroll
    for (int it = 0; it < 8; it++) {
        int idx = tid + it * 256;
        int r = idx >> 4, v = idx & 15;
        *reinterpret_cast<uint4*>(dst + r * SKA + v * 8) =
            *reinterpret_cast<const uint4*>(src + (size_t)r * DMODEL + v * 8);
    }
}

// compute S fragments for one 128-token chunk (8 k16 steps over HDIM),
// with the reference's bf16-round then bf16-scale applied.
__device__ __forceinline__ void s_chunk_mma(float sacc[2][8][4],
                                            const uint32_t aB[2], const uint32_t bB[4],
                                            float scale_b) {
    #pragma unroll
    for (int mt = 0; mt < 2; mt++)
        #pragma unroll
        for (int ng = 0; ng < 8; ng++)
            #pragma unroll
            for (int e = 0; e < 4; e++) sacc[mt][ng][e] = 0.f;
    #pragma unroll
    for (int ks = 0; ks < 8; ks++) {
        uint32_t a[2][4];
        #pragma unroll
        for (int mt = 0; mt < 2; mt++)
            ldmatrix_x4(a[mt][0], a[mt][1], a[mt][2], a[mt][3], aB[mt] + ks * 32);
        uint32_t bf8[8][2];
        #pragma unroll
        for (int nt = 0; nt < 4; nt++) {
            uint32_t r0, r1, r2, r3;
            ldmatrix_x4(r0, r1, r2, r3, bB[nt] + ks * 32);
            bf8[nt * 2 + 0][0] = r0; bf8[nt * 2 + 0][1] = r2;
            bf8[nt * 2 + 1][0] = r1; bf8[nt * 2 + 1][1] = r3;
        }
        #pragma unroll
        for (int mt = 0; mt < 2; mt++)
            #pragma unroll
            for (int ng = 0; ng < 8; ng++)
                mma16816(sacc[mt][ng], a[mt], bf8[ng]);
    }
    #pragma unroll
    for (int mt = 0; mt < 2; mt++)
        #pragma unroll
        for (int ng = 0; ng < 8; ng++)
            #pragma unroll
            for (int e = 0; e < 4; e++) {
                float t = __bfloat162float(__float2bfloat16(sacc[mt][ng][e]));
                sacc[mt][ng][e] = __bfloat162float(__float2bfloat16(t * scale_b));
            }
}

// Pass A: exact per-row max / sumexp over all 2048 keys
__global__ __launch_bounds__(256) void k_attn_stats_mma()
{
    extern __shared__ __align__(16) char dynsm[];
    __nv_bfloat16* sQ = (__nv_bfloat16*)dynsm;
    __nv_bfloat16* sK = (__nv_bfloat16*)(dynsm + AQ_BYTES);
    float* pm = (float*)(dynsm + 2 * AQ_BYTES);            // [2][128]
    float* pl = (float*)(dynsm + 2 * AQ_BYTES + 1024);     // [2][128]
    float* mr = (float*)(dynsm + 2 * AQ_BYTES + 2048);     // [128]
    float* lr = (float*)(dynsm + 2 * AQ_BYTES + 2560);     // [128]

    const int tid = threadIdx.x, lane = tid & 31, wid = tid >> 5;
    const int wm = wid & 3, wn = wid >> 2;
    const int quad = lane >> 2, qt = lane & 3;
    const int qt0 = blockIdx.x, bh = blockIdx.y, b = bh >> 4, hh = bh & 15;
    const float scale_b = __bfloat162float(__float2bfloat16(0.08838834764831845f));

    const __nv_bfloat16* Qg = g_Q + ((size_t)(b * SEQ + qt0 * 128)) * DMODEL + hh * HDIM;
    const __nv_bfloat16* Kg = g_K + (size_t)(b * SEQ) * DMODEL + hh * HDIM;

    tile_copy(sQ, Qg, tid);
    if (tid < 128) { mr[tid] = -3.0e38f; lr[tid] = 0.f; }

    const int rsel = (lane & 7) + ((lane >> 3) & 1) * 8;
    const int csel = (lane >> 4) * 8;
    uint32_t aB[2], bB[4];
    #pragma unroll
    for (int mt = 0; mt < 2; mt++)
        aB[mt] = smem_u32(sQ + (wm * 32 + mt * 16 + rsel) * SKA + csel);
    #pragma unroll
    for (int nt = 0; nt < 4; nt++)
        bB[nt] = smem_u32(sK + (wn * 64 + nt * 16 + rsel) * SKA + csel);

    for (int kt = 0; kt < 16; kt++) {
        __syncthreads();
        tile_copy(sK, Kg + (size_t)(kt * 128) * DMODEL, tid);
        __syncthreads();
        float sacc[2][8][4];
        s_chunk_mma(sacc, aB, bB, scale_b);
        #pragma unroll
        for (int mt = 0; mt < 2; mt++)
            #pragma unroll
            for (int h = 0; h < 2; h++) {
                float cmax = -3.0e38f;
                #pragma unroll
                for (int ng = 0; ng < 8; ng++)
                    cmax = fmaxf(cmax, fmaxf(sacc[mt][ng][h*2], sacc[mt][ng][h*2+1]));
                cmax = fmaxf(cmax, __shfl_xor_sync(0xffffffffu, cmax, 1));
                cmax = fmaxf(cmax, __shfl_xor_sync(0xffffffffu, cmax, 2));
                float cl = 0.f;
                #pragma unroll
                for (int ng = 0; ng < 8; ng++)
                    cl += expf(sacc[mt][ng][h*2] - cmax) + expf(sacc[mt][ng][h*2+1] - cmax);
                cl += __shfl_xor_sync(0xffffffffu, cl, 1);
                cl += __shfl_xor_sync(0xffffffffu, cl, 2);
                if (qt == 0) {
                    int row = wm * 32 + mt * 16 + quad + h * 8;
                    pm[wn * 128 + row] = cmax;
                    pl[wn * 128 + row] = cl;
                }
            }
        __syncthreads();
        if (tid < 128) {
            float m0 = pm[tid], m1 = pm[128 + tid];
            float l0 = pl[tid], l1 = pl[128 + tid];
            float cm = fmaxf(m0, m1);
            float cl = l0 * expf(m0 - cm) + l1 * expf(m1 - cm);
            float mo = mr[tid], lo = lr[tid];
            float mn = fmaxf(mo, cm);
            lr[tid] = lo * expf(mo - mn) + cl * expf(cm - mn);
            mr[tid] = mn;
        }
    }
    __syncthreads();
    if (tid < 128) {
        g_m[(size_t)bh * SEQ + qt0 * 128 + tid] = mr[tid];
        g_l[(size_t)bh * SEQ + qt0 * 128 + tid] = lr[tid];
    }
}

// Pass B: recompute S, quantize P to e4m3, O = P @ V on tensor cores
__global__ __launch_bounds__(256) void k_attn_av_mma()
{
    extern __shared__ __align__(16) char dynsm[];
    __nv_bfloat16* sQ  = (__nv_bfloat16*)dynsm;
    __nv_bfloat16* sKV = (__nv_bfloat16*)(dynsm + AQ_BYTES);
    __nv_bfloat16* sP  = (__nv_bfloat16*)(dynsm + 2 * AQ_BYTES);
    float* sm = (float*)(dynsm + 3 * AQ_BYTES);            // [128]
    float* sl = (float*)(dynsm + 3 * AQ_BYTES + 512);      // [128]

    const int tid = threadIdx.x, lane = tid & 31, wid = tid >> 5;
    const int wm = wid & 3, wn = wid >> 2;
    const int quad = lane >> 2, qt = lane & 3;
    const int qt0 = blockIdx.x, bh = blockIdx.y, b = bh >> 4, hh = bh & 15;
    const float scale_b = __bfloat162float(__float2bfloat16(0.08838834764831845f));

    const __nv_bfloat16* Qg = g_Q + ((size_t)(b * SEQ + qt0 * 128)) * DMODEL + hh * HDIM;
    const __nv_bfloat16* Kg = g_K + (size_t)(b * SEQ) * DMODEL + hh * HDIM;
    const __nv_bfloat16* Vg = g_V + (size_t)(b * SEQ) * DMODEL + hh * HDIM;

    tile_copy(sQ, Qg, tid);
    if (tid < 128) {
        sm[tid] = g_m[(size_t)bh * SEQ + qt0 * 128 + tid];
        sl[tid] = g_l[(size_t)bh * SEQ + qt0 * 128 + tid];
    }
    __syncthreads();

    // per-thread row stats (rows: wm*32 + mt*16 + quad + h*8)
    float mrow[2][2], lrow[2][2];
    #pragma unroll
    for (int mt = 0; mt < 2; mt++)
        #pragma unroll
        for (int h = 0; h < 2; h++) {
            int row = wm * 32 + mt * 16 + quad + h * 8;
            mrow[mt][h] = sm[row];
            lrow[mt][h] = sl[row];
        }

    const int rsel = (lane & 7) + ((lane >> 3) & 1) * 8;
    const int csel = (lane >> 4) * 8;
    const int rselT = (lane & 7) + ((lane >> 4) & 1) * 8;   // V-trans selectors
    const int cselT = ((lane >> 3) & 1) * 8;
    uint32_t aB[2], bB[4], pB[2], vB[4];
    #pragma unroll
    for (int mt = 0; mt < 2; mt++) {
        aB[mt] = smem_u32(sQ + (wm * 32 + mt * 16 + rsel) * SKA + csel);
        pB[mt] = smem_u32(sP + (wm * 32 + mt * 16 + rsel) * SKA + csel);
    }
    #pragma unroll
    for (int nt = 0; nt < 4; nt++) {
        bB[nt] = smem_u32(sKV + (wn * 64 + nt * 16 + rsel) * SKA + csel);
        vB[nt] = smem_u32(sKV + rselT * SKA + wn * 64 + nt * 16 + cselT);
    }

    float oacc[2][8][4] = {};

    for (int kt = 0; kt < 16; kt++) {
        __syncthreads();                       // prior PV reads of sKV/sP done
        tile_copy(sKV, Kg + (size_t)(kt * 128) * DMODEL, tid);
        __syncthreads();
        float sacc[2][8][4];
        s_chunk_mma(sacc, aB, bB, scale_b);
        // P = e4m3(bf16(exp(s-m)/l)), packed bf16x2 into sP
        #pragma unroll
        for (int mt = 0; mt < 2; mt++)
            #pragma unroll
            for (int ng = 0; ng < 8; ng++)
                #pragma unroll
                for (int h = 0; h < 2; h++) {
                    float p0 = expf(sacc[mt][ng][h*2]   - mrow[mt][h]) / lrow[mt][h];
                    float p1 = expf(sacc[mt][ng][h*2+1] - mrow[mt][h]) / lrow[mt][h];
                    __nv_bfloat162 pq = __halves2bfloat162(
                        __float2bfloat16(fp8_round_bf(p0)),
                        __float2bfloat16(fp8_round_bf(p1)));
                    int row = wm * 32 + mt * 16 + quad + h * 8;
                    int col = wn * 64 + ng * 8 + qt * 2;
                    *reinterpret_cast<__nv_bfloat162*>(sP + row * SKA + col) = pq;
                }
        __syncthreads();                       // P visible; S-mma reads of sKV done
        tile_copy(sKV, Vg + (size_t)(kt * 128) * DMODEL, tid);
        __syncthreads();
        // O += P[128 x 128tok] @ V[128tok x 128hd]
        #pragma unroll
        for (int ks = 0; ks < 8; ks++) {
            uint32_t a[2][4];
            #pragma unroll
            for (int mt = 0; mt < 2; mt++)
                ldmatrix_x4(a[mt][0], a[mt][1], a[mt][2], a[mt][3], pB[mt] + ks * 32);
            uint32_t bf8[8][2];
            #pragma unroll
            for (int nt = 0; nt < 4; nt++) {
                uint32_t r0, r1, r2, r3;
                ldmatrix_x4_trans(r0, r1, r2, r3, vB[nt] + ks * 16 * SKA * 2);
                bf8[nt * 2 + 0][0] = r0; bf8[nt * 2 + 0][1] = r2;
                bf8[nt * 2 + 1][0] = r1; bf8[nt * 2 + 1][1] = r3;
            }
            #pragma unroll
            for (int mt = 0; mt < 2; mt++)
                #pragma unroll
                for (int ng = 0; ng < 8; ng++)
                    mma16816(oacc[mt][ng], a[mt], bf8[ng]);
        }
    }

    // epilogue: AO = bf16(e4m3(bf16(acc)))
    #pragma unroll
    for (int mt = 0; mt < 2; mt++)
        #pragma unroll
        for (int ng = 0; ng < 8; ng++)
            #pragma unroll
            for (int h = 0; h < 2; h++) {
                int row = qt0 * 128 + wm * 32 + mt * 16 + quad + h * 8;
                int col = wn * 64 + ng * 8 + qt * 2;
                __nv_bfloat162 o = __halves2bfloat162(
                    __float2bfloat16(fp8_round_bf(oacc[mt][ng][h*2])),
                    __float2bfloat16(fp8_round_bf(oacc[mt][ng][h*2+1])));
                *reinterpret_cast<__nv_bfloat162*>(
                    g_AO + (size_t)(b * SEQ + row) * DMODEL + hh * HDIM + col) = o;
            }
}

// ---------------- launch ----------------
extern "C" void kernel_launch(void* const* d_in, const int* in_sizes, int n_in,
                              void* d_out, int out_size)
{
    int iq, ikv, iwq, iwk, iwv, iwo;
    if (in_sizes[0] == NACT) {           // signature / insertion order
        iq = 0; ikv = 1; iwq = 2; iwk = 3; iwv = 4; iwo = 5;
    } else {                             // alphabetically sorted keys
        iwk = 0; iwo = 1; iwq = 2; iwv = 3; ikv = 4; iq = 5;
    }
    const float* in_q  = (const float*)d_in[iq];
    const float* in_kv = (const float*)d_in[ikv];
    const float* wq = (const float*)d_in[iwq];
    const float* wk = (const float*)d_in[iwk];
    const float* wv = (const float*)d_in[iwv];
    const float* wo = (const float*)d_in[iwo];

    __nv_bfloat16 *xq, *xkv, *wqe, *wke, *wve, *woe, *q, *k, *v, *ao;
    cudaGetSymbolAddress((void**)&xq,  g_Xq);
    cudaGetSymbolAddress((void**)&xkv, g_Xkv);
    cudaGetSymbolAddress((void**)&wqe, g_Wq);
    cudaGetSymbolAddress((void**)&wke, g_Wk);
    cudaGetSymbolAddress((void**)&wve, g_Wv);
    cudaGetSymbolAddress((void**)&woe, g_Wo);
    cudaGetSymbolAddress((void**)&q,   g_Q);
    cudaGetSymbolAddress((void**)&k,   g_K);
    cudaGetSymbolAddress((void**)&v,   g_V);
    cudaGetSymbolAddress((void**)&ao,  g_AO);

    // opt-in dynamic SMEM for the attention kernels (idempotent host calls)
    const int SMEM_A = 2 * AQ_BYTES + 3072;       // 72704
    const int SMEM_B = 3 * AQ_BYTES + 1024;       // 105472
    cudaFuncSetAttribute(k_attn_stats_mma, cudaFuncAttributeMaxDynamicSharedMemorySize, SMEM_A);
    cudaFuncSetAttribute(k_attn_av_mma,    cudaFuncAttributeMaxDynamicSharedMemorySize, SMEM_B);

    // quantize activations; transpose+quantize weights (mma B operand is [N,K])
    k_quant_f32<<<NACT / 256, 256>>>(in_q,  xq,  NACT);
    k_quant_f32<<<NACT / 256, 256>>>(in_kv, xkv, NACT);
    dim3 gt(DMODEL / 32, DMODEL / 32);
    k_wtrans<<<gt, 1024>>>(wq, wqe);
    k_wtrans<<<gt, 1024>>>(wk, wke);
    k_wtrans<<<gt, 1024>>>(wv, wve);
    k_wtrans<<<gt, 1024>>>(wo, woe);

    // projections on tensor cores (V fuses e4m3 re-quant into epilogue)
    dim3 gg(DMODEL / TBN, MROWS / TBM);
    k_gemm_mma<<<gg, 256>>>(xq,  wqe, q, MROWS, DMODEL, DMODEL, 0);
    k_gemm_mma<<<gg, 256>>>(xkv, wke, k, MROWS, DMODEL, DMODEL, 0);
    k_gemm_mma<<<gg, 256>>>(xkv, wve, v, MROWS, DMODEL, DMODEL, 1);

    // attention on tensor cores: stats pass then AV pass
    dim3 ga(SEQ / 128, BATCH * NHEAD);
    k_attn_stats_mma<<<ga, 256, SMEM_A>>>();
    k_attn_av_mma<<<ga, 256, SMEM_B>>>();

    // output projection: bf16-rounded values widened to FLOAT32 output buffer
    k_gemm_mma<<<gg, 256>>>(ao, woe, d_out, MROWS, DMODEL, DMODEL, 2);
}

// round 13
// speedup vs baseline: 10.0022x; 1.0243x over previous
#include <cuda_runtime.h>
#include <cuda_bf16.h>
#include <cuda_fp8.h>
#include <cstdint>
#include <cstddef>

// Problem shape (fixed by the dataset)
#define BATCH  2
#define SEQ    2048
#define DMODEL 2048
#define NHEAD  16
#define HDIM   128
#define MROWS  (BATCH*SEQ)       // 4096
#define NACT   (MROWS*DMODEL)    // 8388608
#define NWEI   (DMODEL*DMODEL)   // 4194304

// ---------------- scratch: __device__ globals (no dynamic allocation) ----------
__device__ __nv_bfloat16 g_Xq [NACT];
__device__ __nv_bfloat16 g_Xkv[NACT];
__device__ __nv_bfloat16 g_Wq [NWEI];   // TRANSPOSED [n][k], e4m3-rounded bf16
__device__ __nv_bfloat16 g_Wk [NWEI];
__device__ __nv_bfloat16 g_Wv [NWEI];
__device__ __nv_bfloat16 g_Wo [NWEI];
__device__ __nv_bfloat16 g_Q  [NACT];
__device__ __nv_bfloat16 g_K  [NACT];
__device__ __nv_bfloat16 g_V  [NACT];
__device__ __nv_bfloat16 g_AO [NACT];
__device__ float g_m[BATCH*NHEAD*SEQ];
__device__ float g_l[BATCH*NHEAD*SEQ];

// ---------------- small helpers ----------------
__device__ __forceinline__ uint32_t smem_u32(const void* p) {
    uint32_t a;
    asm("{ .reg .u64 t; cvta.to.shared.u64 t, %1; cvt.u32.u64 %0, t; }" : "=r"(a) : "l"(p));
    return a;
}
__device__ __forceinline__ void ldmatrix_x4(uint32_t& r0, uint32_t& r1,
                                            uint32_t& r2, uint32_t& r3, uint32_t addr) {
    asm volatile("ldmatrix.sync.aligned.m8n8.x4.shared.b16 {%0,%1,%2,%3}, [%4];"
                 : "=r"(r0), "=r"(r1), "=r"(r2), "=r"(r3) : "r"(addr));
}
__device__ __forceinline__ void ldmatrix_x4_trans(uint32_t& r0, uint32_t& r1,
                                                  uint32_t& r2, uint32_t& r3, uint32_t addr) {
    asm volatile("ldmatrix.sync.aligned.m8n8.x4.trans.shared.b16 {%0,%1,%2,%3}, [%4];"
                 : "=r"(r0), "=r"(r1), "=r"(r2), "=r"(r3) : "r"(addr));
}
__device__ __forceinline__ void mma16816(float* c, const uint32_t* a, const uint32_t* b) {
    asm volatile(
        "mma.sync.aligned.m16n8k16.row.col.f32.bf16.bf16.f32 "
        "{%0,%1,%2,%3}, {%4,%5,%6,%7}, {%8,%9}, {%0,%1,%2,%3};"
        : "+f"(c[0]), "+f"(c[1]), "+f"(c[2]), "+f"(c[3])
        : "r"(a[0]), "r"(a[1]), "r"(a[2]), "r"(a[3]), "r"(b[0]), "r"(b[1]));
}
__device__ __forceinline__ void cp_async16(uint32_t saddr, const void* gaddr) {
    asm volatile("cp.async.cg.shared.global [%0], [%1], 16;" :: "r"(saddr), "l"(gaddr));
}

// ---------------- fp8 helpers ----------------
__device__ __forceinline__ float fp8_round(float x) {
    __nv_fp8_storage_t r = __nv_cvt_float_to_fp8(x, __NV_SATFINITE, __NV_E4M3);
    __half_raw hr = __nv_cvt_fp8_to_halfraw(r, __NV_E4M3);
    return __half2float(__half(hr));
}
__device__ __forceinline__ float fp8_round_bf(float x) {
    float xb = __bfloat162float(__float2bfloat16(x));
    return fp8_round(xb);
}

// ---------------- quantize / transpose kernels ----------------
__global__ void k_quant_f32(const float* __restrict__ in, __nv_bfloat16* __restrict__ out, int n) {
    int i = blockIdx.x * blockDim.x + threadIdx.x;
    if (i < n) out[i] = __float2bfloat16(fp8_round(in[i]));
}
__global__ __launch_bounds__(1024) void k_wtrans(const float* __restrict__ W,
                                                 __nv_bfloat16* __restrict__ Wt) {
    __shared__ float t[32][33];
    int tx = threadIdx.x & 31, ty = threadIdx.x >> 5;
    int n0 = blockIdx.x * 32, k0 = blockIdx.y * 32;
    t[ty][tx] = W[(size_t)(k0 + ty) * DMODEL + n0 + tx];
    __syncthreads();
    Wt[(size_t)(n0 + ty) * DMODEL + k0 + tx] = __float2bfloat16(fp8_round(t[tx][ty]));
}

// ---------------- mma.sync dense GEMM: 3-stage cp.async pipeline ----------------
// C[M,N] = A[M,K] @ Bt[N,K]^T  (bf16 in, fp32 accum)
// epi: 0 = bf16(acc), 1 = bf16(e4m3(bf16(acc))) [V path], 2 = f32(bf16(acc)) [final]
#define TBM 128
#define TBN 128
#define TBK 32
#define SKP 40          // padded row (bf16): 80B stride, ldmatrix conflict-free
#define GTILE (TBM*SKP*2)       // 10240 B per operand tile
#define GSTG  (2*GTILE)         // 20480 B per stage (A+B)
#define GSMEM (3*GSTG)          // 61440 B dynamic
__global__ __launch_bounds__(256, 2) void k_gemm_mma(const __nv_bfloat16* __restrict__ A,
                                                     const __nv_bfloat16* __restrict__ Bt,
                                                     void* __restrict__ C,
                                                     int M, int N, int K, int epi)
{
    extern __shared__ __align__(16) char gsm[];
    const uint32_t smemBase = smem_u32(gsm);
    const int tid = threadIdx.x, wid = tid >> 5, lane = tid & 31;
    const int wm = wid & 3, wn = wid >> 2;
    const int row0 = blockIdx.y * TBM, col0 = blockIdx.x * TBN;
    const int rsel = (lane & 7) + ((lane >> 3) & 1) * 8;
    const int csel = (lane >> 4) * 8;

    // ldmatrix byte offsets relative to stage base (add ks*32 bytes for ks=1)
    uint32_t aOff[2], bOff[4];
    #pragma unroll
    for (int mt = 0; mt < 2; mt++)
        aOff[mt] = ((wm * 32 + mt * 16 + rsel) * SKP + csel) * 2;
    #pragma unroll
    for (int nt = 0; nt < 4; nt++)
        bOff[nt] = GTILE + ((wn * 64 + nt * 16 + rsel) * SKP + csel) * 2;

    // per-thread load coords (4 cp.async per stage: 2 for A, 2 for B)
    const int lr0 = tid >> 2, lcg = (tid & 3) * 8;      // rows 0..63
    const int lr1 = lr0 + 64;                           // rows 64..127

    const int nch = K / TBK;   // 64

    // stage issue: chunk ch -> stage stg
    auto issue = [&](int ch, int stg) {
        uint32_t sA = smemBase + stg * GSTG;
        uint32_t sB = sA + GTILE;
        int kk = ch * TBK;
        cp_async16(sA + (lr0 * SKP + lcg) * 2, A  + (size_t)(row0 + lr0) * K + kk + lcg);
        cp_async16(sA + (lr1 * SKP + lcg) * 2, A  + (size_t)(row0 + lr1) * K + kk + lcg);
        cp_async16(sB + (lr0 * SKP + lcg) * 2, Bt + (size_t)(col0 + lr0) * K + kk + lcg);
        cp_async16(sB + (lr1 * SKP + lcg) * 2, Bt + (size_t)(col0 + lr1) * K + kk + lcg);
        asm volatile("cp.async.commit_group;" ::: "memory");
    };

    float acc[2][8][4] = {};

    issue(0, 0);
    issue(1, 1);
    for (int i = 0; i < nch; i++) {
        if (i < nch - 1) asm volatile("cp.async.wait_group 1;" ::: "memory");
        else             asm volatile("cp.async.wait_group 0;" ::: "memory");
        __syncthreads();
        if (i + 2 < nch) issue(i + 2, (i + 2) % 3);   // overwrites stage (i-1)%3: readers passed barrier
        uint32_t sbase = smemBase + (i % 3) * GSTG;
        #pragma unroll
        for (int ks = 0; ks < 2; ks++) {
            uint32_t a[2][4];
            #pragma unroll
            for (int mt = 0; mt < 2; mt++)
                ldmatrix_x4(a[mt][0], a[mt][1], a[mt][2], a[mt][3], sbase + aOff[mt] + ks * 32);
            uint32_t bf[8][2];
            #pragma unroll
            for (int nt = 0; nt < 4; nt++) {
                uint32_t r0, r1, r2, r3;
                ldmatrix_x4(r0, r1, r2, r3, sbase + bOff[nt] + ks * 32);
                bf[nt * 2 + 0][0] = r0; bf[nt * 2 + 0][1] = r2;
                bf[nt * 2 + 1][0] = r1; bf[nt * 2 + 1][1] = r3;
            }
            #pragma unroll
            for (int mt = 0; mt < 2; mt++)
                #pragma unroll
                for (int ng = 0; ng < 8; ng++)
                    mma16816(acc[mt][ng], a[mt], bf[ng]);
        }
    }

    const int quad = lane >> 2, qt = lane & 3;
    #pragma unroll
    for (int mt = 0; mt < 2; mt++) {
        #pragma unroll
        for (int ng = 0; ng < 8; ng++) {
            int r0 = row0 + wm * 32 + mt * 16 + quad;
            int c  = col0 + wn * 64 + ng * 8 + qt * 2;
            #pragma unroll
            for (int h = 0; h < 2; h++) {
                size_t r = (size_t)(r0 + h * 8);
                float v0 = acc[mt][ng][h * 2 + 0];
                float v1 = acc[mt][ng][h * 2 + 1];
                if (epi == 2) {
                    float2 o;
                    o.x = __bfloat162float(__float2bfloat16(v0));
                    o.y = __bfloat162float(__float2bfloat16(v1));
                    *reinterpret_cast<float2*>((float*)C + r * N + c) = o;
                } else {
                    __nv_bfloat16 b0 = __float2bfloat16(v0);
                    __nv_bfloat16 b1 = __float2bfloat16(v1);
                    if (epi == 1) {
                        b0 = __float2bfloat16(fp8_round(__bfloat162float(b0)));
                        b1 = __float2bfloat16(fp8_round(__bfloat162float(b1)));
                    }
                    __nv_bfloat162 o = __halves2bfloat162(b0, b1);
                    *reinterpret_cast<__nv_bfloat162*>((__nv_bfloat16*)C + r * N + c) = o;
                }
            }
        }
    }
}

// ================= attention on mma.sync (validated round 10) =================
#define SKA 136
#define AQ_BYTES  (128*SKA*2)   // 34816

__device__ __forceinline__ void tile_copy(__nv_bfloat16* dst, const __nv_bfloat16* src, int tid) {
    #pragma unroll
    for (int it = 0; it < 8; it++) {
        int idx = tid + it * 256;
        int r = idx >> 4, v = idx & 15;
        *reinterpret_cast<uint4*>(dst + r * SKA + v * 8) =
            *reinterpret_cast<const uint4*>(src + (size_t)r * DMODEL + v * 8);
    }
}

__device__ __forceinline__ void s_chunk_mma(float sacc[2][8][4],
                                            const uint32_t aB[2], const uint32_t bB[4],
                                            float scale_b) {
    #pragma unroll
    for (int mt = 0; mt < 2; mt++)
        #pragma unroll
        for (int ng = 0; ng < 8; ng++)
            #pragma unroll
            for (int e = 0; e < 4; e++) sacc[mt][ng][e] = 0.f;
    #pragma unroll
    for (int ks = 0; ks < 8; ks++) {
        uint32_t a[2][4];
        #pragma unroll
        for (int mt = 0; mt < 2; mt++)
            ldmatrix_x4(a[mt][0], a[mt][1], a[mt][2], a[mt][3], aB[mt] + ks * 32);
        uint32_t bf8[8][2];
        #pragma unroll
        for (int nt = 0; nt < 4; nt++) {
            uint32_t r0, r1, r2, r3;
            ldmatrix_x4(r0, r1, r2, r3, bB[nt] + ks * 32);
            bf8[nt * 2 + 0][0] = r0; bf8[nt * 2 + 0][1] = r2;
            bf8[nt * 2 + 1][0] = r1; bf8[nt * 2 + 1][1] = r3;
        }
        #pragma unroll
        for (int mt = 0; mt < 2; mt++)
            #pragma unroll
            for (int ng = 0; ng < 8; ng++)
                mma16816(sacc[mt][ng], a[mt], bf8[ng]);
    }
    #pragma unroll
    for (int mt = 0; mt < 2; mt++)
        #pragma unroll
        for (int ng = 0; ng < 8; ng++)
            #pragma unroll
            for (int e = 0; e < 4; e++) {
                float t = __bfloat162float(__float2bfloat16(sacc[mt][ng][e]));
                sacc[mt][ng][e] = __bfloat162float(__float2bfloat16(t * scale_b));
            }
}

// Pass A: exact per-row max / sumexp over all 2048 keys
__global__ __launch_bounds__(256) void k_attn_stats_mma()
{
    extern __shared__ __align__(16) char dynsm[];
    __nv_bfloat16* sQ = (__nv_bfloat16*)dynsm;
    __nv_bfloat16* sK = (__nv_bfloat16*)(dynsm + AQ_BYTES);
    float* pm = (float*)(dynsm + 2 * AQ_BYTES);            // [2][128]
    float* pl = (float*)(dynsm + 2 * AQ_BYTES + 1024);     // [2][128]
    float* mr = (float*)(dynsm + 2 * AQ_BYTES + 2048);     // [128]
    float* lr = (float*)(dynsm + 2 * AQ_BYTES + 2560);     // [128]

    const int tid = threadIdx.x, lane = tid & 31, wid = tid >> 5;
    const int wm = wid & 3, wn = wid >> 2;
    const int quad = lane >> 2, qt = lane & 3;
    const int qt0 = blockIdx.x, bh = blockIdx.y, b = bh >> 4, hh = bh & 15;
    const float scale_b = __bfloat162float(__float2bfloat16(0.08838834764831845f));

    const __nv_bfloat16* Qg = g_Q + ((size_t)(b * SEQ + qt0 * 128)) * DMODEL + hh * HDIM;
    const __nv_bfloat16* Kg = g_K + (size_t)(b * SEQ) * DMODEL + hh * HDIM;

    tile_copy(sQ, Qg, tid);
    if (tid < 128) { mr[tid] = -3.0e38f; lr[tid] = 0.f; }

    const int rsel = (lane & 7) + ((lane >> 3) & 1) * 8;
    const int csel = (lane >> 4) * 8;
    uint32_t aB[2], bB[4];
    #pragma unroll
    for (int mt = 0; mt < 2; mt++)
        aB[mt] = smem_u32(sQ + (wm * 32 + mt * 16 + rsel) * SKA + csel);
    #pragma unroll
    for (int nt = 0; nt < 4; nt++)
        bB[nt] = smem_u32(sK + (wn * 64 + nt * 16 + rsel) * SKA + csel);

    for (int kt = 0; kt < 16; kt++) {
        __syncthreads();
        tile_copy(sK, Kg + (size_t)(kt * 128) * DMODEL, tid);
        __syncthreads();
        float sacc[2][8][4];
        s_chunk_mma(sacc, aB, bB, scale_b);
        #pragma unroll
        for (int mt = 0; mt < 2; mt++)
            #pragma unroll
            for (int h = 0; h < 2; h++) {
                float cmax = -3.0e38f;
                #pragma unroll
                for (int ng = 0; ng < 8; ng++)
                    cmax = fmaxf(cmax, fmaxf(sacc[mt][ng][h*2], sacc[mt][ng][h*2+1]));
                cmax = fmaxf(cmax, __shfl_xor_sync(0xffffffffu, cmax, 1));
                cmax = fmaxf(cmax, __shfl_xor_sync(0xffffffffu, cmax, 2));
                float cl = 0.f;
                #pragma unroll
                for (int ng = 0; ng < 8; ng++)
                    cl += expf(sacc[mt][ng][h*2] - cmax) + expf(sacc[mt][ng][h*2+1] - cmax);
                cl += __shfl_xor_sync(0xffffffffu, cl, 1);
                cl += __shfl_xor_sync(0xffffffffu, cl, 2);
                if (qt == 0) {
                    int row = wm * 32 + mt * 16 + quad + h * 8;
                    pm[wn * 128 + row] = cmax;
                    pl[wn * 128 + row] = cl;
                }
            }
        __syncthreads();
        if (tid < 128) {
            float m0 = pm[tid], m1 = pm[128 + tid];
            float l0 = pl[tid], l1 = pl[128 + tid];
            float cm = fmaxf(m0, m1);
            float cl = l0 * expf(m0 - cm) + l1 * expf(m1 - cm);
            float mo = mr[tid], lo = lr[tid];
            float mn = fmaxf(mo, cm);
            lr[tid] = lo * expf(mo - mn) + cl * expf(cm - mn);
            mr[tid] = mn;
        }
    }
    __syncthreads();
    if (tid < 128) {
        g_m[(size_t)bh * SEQ + qt0 * 128 + tid] = mr[tid];
        g_l[(size_t)bh * SEQ + qt0 * 128 + tid] = lr[tid];
    }
}

// Pass B: recompute S, quantize P to e4m3, O = P @ V on tensor cores
__global__ __launch_bounds__(256) void k_attn_av_mma()
{
    extern __shared__ __align__(16) char dynsm[];
    __nv_bfloat16* sQ  = (__nv_bfloat16*)dynsm;
    __nv_bfloat16* sKV = (__nv_bfloat16*)(dynsm + AQ_BYTES);
    __nv_bfloat16* sP  = (__nv_bfloat16*)(dynsm + 2 * AQ_BYTES);
    float* sm = (float*)(dynsm + 3 * AQ_BYTES);            // [128]
    float* sl = (float*)(dynsm + 3 * AQ_BYTES + 512);      // [128]

    const int tid = threadIdx.x, lane = tid & 31, wid = tid >> 5;
    const int wm = wid & 3, wn = wid >> 2;
    const int quad = lane >> 2, qt = lane & 3;
    const int qt0 = blockIdx.x, bh = blockIdx.y, b = bh >> 4, hh = bh & 15;
    const float scale_b = __bfloat162float(__float2bfloat16(0.08838834764831845f));

    const __nv_bfloat16* Qg = g_Q + ((size_t)(b * SEQ + qt0 * 128)) * DMODEL + hh * HDIM;
    const __nv_bfloat16* Kg = g_K + (size_t)(b * SEQ) * DMODEL + hh * HDIM;
    const __nv_bfloat16* Vg = g_V + (size_t)(b * SEQ) * DMODEL + hh * HDIM;

    tile_copy(sQ, Qg, tid);
    if (tid < 128) {
        sm[tid] = g_m[(size_t)bh * SEQ + qt0 * 128 + tid];
        sl[tid] = g_l[(size_t)bh * SEQ + qt0 * 128 + tid];
    }
    __syncthreads();

    float mrow[2][2], lrow[2][2];
    #pragma unroll
    for (int mt = 0; mt < 2; mt++)
        #pragma unroll
        for (int h = 0; h < 2; h++) {
            int row = wm * 32 + mt * 16 + quad + h * 8;
            mrow[mt][h] = sm[row];
            lrow[mt][h] = sl[row];
        }

    const int rsel = (lane & 7) + ((lane >> 3) & 1) * 8;
    const int csel = (lane >> 4) * 8;
    const int rselT = (lane & 7) + ((lane >> 4) & 1) * 8;   // V-trans selectors
    const int cselT = ((lane >> 3) & 1) * 8;
    uint32_t aB[2], bB[4], pB[2], vB[4];
    #pragma unroll
    for (int mt = 0; mt < 2; mt++) {
        aB[mt] = smem_u32(sQ + (wm * 32 + mt * 16 + rsel) * SKA + csel);
        pB[mt] = smem_u32(sP + (wm * 32 + mt * 16 + rsel) * SKA + csel);
    }
    #pragma unroll
    for (int nt = 0; nt < 4; nt++) {
        bB[nt] = smem_u32(sKV + (wn * 64 + nt * 16 + rsel) * SKA + csel);
        vB[nt] = smem_u32(sKV + rselT * SKA + wn * 64 + nt * 16 + cselT);
    }

    float oacc[2][8][4] = {};

    for (int kt = 0; kt < 16; kt++) {
        __syncthreads();
        tile_copy(sKV, Kg + (size_t)(kt * 128) * DMODEL, tid);
        __syncthreads();
        float sacc[2][8][4];
        s_chunk_mma(sacc, aB, bB, scale_b);
        #pragma unroll
        for (int mt = 0; mt < 2; mt++)
            #pragma unroll
            for (int ng = 0; ng < 8; ng++)
                #pragma unroll
                for (int h = 0; h < 2; h++) {
                    float p0 = expf(sacc[mt][ng][h*2]   - mrow[mt][h]) / lrow[mt][h];
                    float p1 = expf(sacc[mt][ng][h*2+1] - mrow[mt][h]) / lrow[mt][h];
                    __nv_bfloat162 pq = __halves2bfloat162(
                        __float2bfloat16(fp8_round_bf(p0)),
                        __float2bfloat16(fp8_round_bf(p1)));
                    int row = wm * 32 + mt * 16 + quad + h * 8;
                    int col = wn * 64 + ng * 8 + qt * 2;
                    *reinterpret_cast<__nv_bfloat162*>(sP + row * SKA + col) = pq;
                }
        __syncthreads();
        tile_copy(sKV, Vg + (size_t)(kt * 128) * DMODEL, tid);
        __syncthreads();
        #pragma unroll
        for (int ks = 0; ks < 8; ks++) {
            uint32_t a[2][4];
            #pragma unroll
            for (int mt = 0; mt < 2; mt++)
                ldmatrix_x4(a[mt][0], a[mt][1], a[mt][2], a[mt][3], pB[mt] + ks * 32);
            uint32_t bf8[8][2];
            #pragma unroll
            for (int nt = 0; nt < 4; nt++) {
                uint32_t r0, r1, r2, r3;
                ldmatrix_x4_trans(r0, r1, r2, r3, vB[nt] + ks * 16 * SKA * 2);
                bf8[nt * 2 + 0][0] = r0; bf8[nt * 2 + 0][1] = r2;
                bf8[nt * 2 + 1][0] = r1; bf8[nt * 2 + 1][1] = r3;
            }
            #pragma unroll
            for (int mt = 0; mt < 2; mt++)
                #pragma unroll
                for (int ng = 0; ng < 8; ng++)
                    mma16816(oacc[mt][ng], a[mt], bf8[ng]);
        }
    }

    #pragma unroll
    for (int mt = 0; mt < 2; mt++)
        #pragma unroll
        for (int ng = 0; ng < 8; ng++)
            #pragma unroll
            for (int h = 0; h < 2; h++) {
                int row = qt0 * 128 + wm * 32 + mt * 16 + quad + h * 8;
                int col = wn * 64 + ng * 8 + qt * 2;
                __nv_bfloat162 o = __halves2bfloat162(
                    __float2bfloat16(fp8_round_bf(oacc[mt][ng][h*2])),
                    __float2bfloat16(fp8_round_bf(oacc[mt][ng][h*2+1])));
                *reinterpret_cast<__nv_bfloat162*>(
                    g_AO + (size_t)(b * SEQ + row) * DMODEL + hh * HDIM + col) = o;
            }
}

// ---------------- launch ----------------
extern "C" void kernel_launch(void* const* d_in, const int* in_sizes, int n_in,
                              void* d_out, int out_size)
{
    int iq, ikv, iwq, iwk, iwv, iwo;
    if (in_sizes[0] == NACT) {           // signature / insertion order
        iq = 0; ikv = 1; iwq = 2; iwk = 3; iwv = 4; iwo = 5;
    } else {                             // alphabetically sorted keys
        iwk = 0; iwo = 1; iwq = 2; iwv = 3; ikv = 4; iq = 5;
    }
    const float* in_q  = (const float*)d_in[iq];
    const float* in_kv = (const float*)d_in[ikv];
    const float* wq = (const float*)d_in[iwq];
    const float* wk = (const float*)d_in[iwk];
    const float* wv = (const float*)d_in[iwv];
    const float* wo = (const float*)d_in[iwo];

    __nv_bfloat16 *xq, *xkv, *wqe, *wke, *wve, *woe, *q, *k, *v, *ao;
    cudaGetSymbolAddress((void**)&xq,  g_Xq);
    cudaGetSymbolAddress((void**)&xkv, g_Xkv);
    cudaGetSymbolAddress((void**)&wqe, g_Wq);
    cudaGetSymbolAddress((void**)&wke, g_Wk);
    cudaGetSymbolAddress((void**)&wve, g_Wv);
    cudaGetSymbolAddress((void**)&woe, g_Wo);
    cudaGetSymbolAddress((void**)&q,   g_Q);
    cudaGetSymbolAddress((void**)&k,   g_K);
    cudaGetSymbolAddress((void**)&v,   g_V);
    cudaGetSymbolAddress((void**)&ao,  g_AO);

    // opt-in dynamic SMEM (idempotent host calls)
    const int SMEM_A = 2 * AQ_BYTES + 3072;       // 72704
    const int SMEM_B = 3 * AQ_BYTES + 1024;       // 105472
    cudaFuncSetAttribute(k_gemm_mma,       cudaFuncAttributeMaxDynamicSharedMemorySize, GSMEM);
    cudaFuncSetAttribute(k_attn_stats_mma, cudaFuncAttributeMaxDynamicSharedMemorySize, SMEM_A);
    cudaFuncSetAttribute(k_attn_av_mma,    cudaFuncAttributeMaxDynamicSharedMemorySize, SMEM_B);

    // quantize activations; transpose+quantize weights (mma B operand is [N,K])
    k_quant_f32<<<NACT / 256, 256>>>(in_q,  xq,  NACT);
    k_quant_f32<<<NACT / 256, 256>>>(in_kv, xkv, NACT);
    dim3 gt(DMODEL / 32, DMODEL / 32);
    k_wtrans<<<gt, 1024>>>(wq, wqe);
    k_wtrans<<<gt, 1024>>>(wk, wke);
    k_wtrans<<<gt, 1024>>>(wv, wve);
    k_wtrans<<<gt, 1024>>>(wo, woe);

    // projections on tensor cores (V fuses e4m3 re-quant into epilogue)
    dim3 gg(DMODEL / TBN, MROWS / TBM);
    k_gemm_mma<<<gg, 256, GSMEM>>>(xq,  wqe, q, MROWS, DMODEL, DMODEL, 0);
    k_gemm_mma<<<gg, 256, GSMEM>>>(xkv, wke, k, MROWS, DMODEL, DMODEL, 0);
    k_gemm_mma<<<gg, 256, GSMEM>>>(xkv, wve, v, MROWS, DMODEL, DMODEL, 1);

    // attention on tensor cores: stats pass then AV pass
    dim3 ga(SEQ / 128, BATCH * NHEAD);
    k_attn_stats_mma<<<ga, 256, SMEM_A>>>();
    k_attn_av_mma<<<ga, 256, SMEM_B>>>();

    // output projection: bf16-rounded values widened to FLOAT32 output buffer
    k_gemm_mma<<<gg, 256, GSMEM>>>(ao, woe, d_out, MROWS, DMODEL, DMODEL, 2);
}

// round 14
// speedup vs baseline: 10.3081x; 1.0306x over previous
#include <cuda_runtime.h>
#include <cuda_bf16.h>
#include <cuda_fp8.h>
#include <cstdint>
#include <cstddef>

// Problem shape (fixed by the dataset)
#define BATCH  2
#define SEQ    2048
#define DMODEL 2048
#define NHEAD  16
#define HDIM   128
#define MROWS  (BATCH*SEQ)       // 4096
#define NACT   (MROWS*DMODEL)    // 8388608
#define NWEI   (DMODEL*DMODEL)   // 4194304

// ---------------- scratch: __device__ globals (no dynamic allocation) ----------
__device__ __nv_bfloat16 g_Xq [NACT];
__device__ __nv_bfloat16 g_Xkv[NACT];
__device__ __nv_bfloat16 g_Wq [NWEI];   // TRANSPOSED [n][k], e4m3-rounded bf16
__device__ __nv_bfloat16 g_Wk [NWEI];
__device__ __nv_bfloat16 g_Wv [NWEI];
__device__ __nv_bfloat16 g_Wo [NWEI];
__device__ __nv_bfloat16 g_Q  [NACT];
__device__ __nv_bfloat16 g_K  [NACT];
__device__ __nv_bfloat16 g_V  [NACT];
__device__ __nv_bfloat16 g_AO [NACT];
__device__ float g_m[BATCH*NHEAD*SEQ];
__device__ float g_l[BATCH*NHEAD*SEQ];

// ---------------- small helpers ----------------
__device__ __forceinline__ uint32_t smem_u32(const void* p) {
    uint32_t a;
    asm("{ .reg .u64 t; cvta.to.shared.u64 t, %1; cvt.u32.u64 %0, t; }" : "=r"(a) : "l"(p));
    return a;
}
__device__ __forceinline__ void ldmatrix_x4(uint32_t& r0, uint32_t& r1,
                                            uint32_t& r2, uint32_t& r3, uint32_t addr) {
    asm volatile("ldmatrix.sync.aligned.m8n8.x4.shared.b16 {%0,%1,%2,%3}, [%4];"
                 : "=r"(r0), "=r"(r1), "=r"(r2), "=r"(r3) : "r"(addr));
}
__device__ __forceinline__ void ldmatrix_x4_trans(uint32_t& r0, uint32_t& r1,
                                                  uint32_t& r2, uint32_t& r3, uint32_t addr) {
    asm volatile("ldmatrix.sync.aligned.m8n8.x4.trans.shared.b16 {%0,%1,%2,%3}, [%4];"
                 : "=r"(r0), "=r"(r1), "=r"(r2), "=r"(r3) : "r"(addr));
}
__device__ __forceinline__ void mma16816(float* c, const uint32_t* a, const uint32_t* b) {
    asm volatile(
        "mma.sync.aligned.m16n8k16.row.col.f32.bf16.bf16.f32 "
        "{%0,%1,%2,%3}, {%4,%5,%6,%7}, {%8,%9}, {%0,%1,%2,%3};"
        : "+f"(c[0]), "+f"(c[1]), "+f"(c[2]), "+f"(c[3])
        : "r"(a[0]), "r"(a[1]), "r"(a[2]), "r"(a[3]), "r"(b[0]), "r"(b[1]));
}
__device__ __forceinline__ void cp_async16(uint32_t saddr, const void* gaddr) {
    asm volatile("cp.async.cg.shared.global [%0], [%1], 16;" :: "r"(saddr), "l"(gaddr));
}
#define CP_COMMIT() asm volatile("cp.async.commit_group;" ::: "memory")
#define CP_WAIT0()  asm volatile("cp.async.wait_group 0;" ::: "memory")
#define CP_WAIT1()  asm volatile("cp.async.wait_group 1;" ::: "memory")

// ---------------- fp8 helpers ----------------
__device__ __forceinline__ float fp8_round(float x) {
    __nv_fp8_storage_t r = __nv_cvt_float_to_fp8(x, __NV_SATFINITE, __NV_E4M3);
    __half_raw hr = __nv_cvt_fp8_to_halfraw(r, __NV_E4M3);
    return __half2float(__half(hr));
}
__device__ __forceinline__ float fp8_round_bf(float x) {
    float xb = __bfloat162float(__float2bfloat16(x));
    return fp8_round(xb);
}

// ---------------- quantize / transpose kernels ----------------
__global__ void k_quant_f32(const float* __restrict__ in, __nv_bfloat16* __restrict__ out, int n) {
    int i = blockIdx.x * blockDim.x + threadIdx.x;
    if (i < n) out[i] = __float2bfloat16(fp8_round(in[i]));
}
__global__ __launch_bounds__(1024) void k_wtrans(const float* __restrict__ W,
                                                 __nv_bfloat16* __restrict__ Wt) {
    __shared__ float t[32][33];
    int tx = threadIdx.x & 31, ty = threadIdx.x >> 5;
    int n0 = blockIdx.x * 32, k0 = blockIdx.y * 32;
    t[ty][tx] = W[(size_t)(k0 + ty) * DMODEL + n0 + tx];
    __syncthreads();
    Wt[(size_t)(n0 + ty) * DMODEL + k0 + tx] = __float2bfloat16(fp8_round(t[tx][ty]));
}

// ---------------- mma.sync dense GEMM: 3-stage cp.async pipeline ----------------
#define TBM 128
#define TBN 128
#define TBK 32
#define SKP 40
#define GTILE (TBM*SKP*2)
#define GSTG  (2*GTILE)
#define GSMEM (3*GSTG)
__global__ __launch_bounds__(256, 2) void k_gemm_mma(const __nv_bfloat16* __restrict__ A,
                                                     const __nv_bfloat16* __restrict__ Bt,
                                                     void* __restrict__ C,
                                                     int M, int N, int K, int epi)
{
    extern __shared__ __align__(16) char gsm[];
    const uint32_t smemBase = smem_u32(gsm);
    const int tid = threadIdx.x, wid = tid >> 5, lane = tid & 31;
    const int wm = wid & 3, wn = wid >> 2;
    const int row0 = blockIdx.y * TBM, col0 = blockIdx.x * TBN;
    const int rsel = (lane & 7) + ((lane >> 3) & 1) * 8;
    const int csel = (lane >> 4) * 8;

    uint32_t aOff[2], bOff[4];
    #pragma unroll
    for (int mt = 0; mt < 2; mt++)
        aOff[mt] = ((wm * 32 + mt * 16 + rsel) * SKP + csel) * 2;
    #pragma unroll
    for (int nt = 0; nt < 4; nt++)
        bOff[nt] = GTILE + ((wn * 64 + nt * 16 + rsel) * SKP + csel) * 2;

    const int lr0 = tid >> 2, lcg = (tid & 3) * 8;
    const int lr1 = lr0 + 64;
    const int nch = K / TBK;

    auto issue = [&](int ch, int stg) {
        uint32_t sA = smemBase + stg * GSTG;
        uint32_t sB = sA + GTILE;
        int kk = ch * TBK;
        cp_async16(sA + (lr0 * SKP + lcg) * 2, A  + (size_t)(row0 + lr0) * K + kk + lcg);
        cp_async16(sA + (lr1 * SKP + lcg) * 2, A  + (size_t)(row0 + lr1) * K + kk + lcg);
        cp_async16(sB + (lr0 * SKP + lcg) * 2, Bt + (size_t)(col0 + lr0) * K + kk + lcg);
        cp_async16(sB + (lr1 * SKP + lcg) * 2, Bt + (size_t)(col0 + lr1) * K + kk + lcg);
        CP_COMMIT();
    };

    float acc[2][8][4] = {};

    issue(0, 0);
    issue(1, 1);
    for (int i = 0; i < nch; i++) {
        if (i < nch - 1) CP_WAIT1();
        else             CP_WAIT0();
        __syncthreads();
        if (i + 2 < nch) issue(i + 2, (i + 2) % 3);
        uint32_t sbase = smemBase + (i % 3) * GSTG;
        #pragma unroll
        for (int ks = 0; ks < 2; ks++) {
            uint32_t a[2][4];
            #pragma unroll
            for (int mt = 0; mt < 2; mt++)
                ldmatrix_x4(a[mt][0], a[mt][1], a[mt][2], a[mt][3], sbase + aOff[mt] + ks * 32);
            uint32_t bf[8][2];
            #pragma unroll
            for (int nt = 0; nt < 4; nt++) {
                uint32_t r0, r1, r2, r3;
                ldmatrix_x4(r0, r1, r2, r3, sbase + bOff[nt] + ks * 32);
                bf[nt * 2 + 0][0] = r0; bf[nt * 2 + 0][1] = r2;
                bf[nt * 2 + 1][0] = r1; bf[nt * 2 + 1][1] = r3;
            }
            #pragma unroll
            for (int mt = 0; mt < 2; mt++)
                #pragma unroll
                for (int ng = 0; ng < 8; ng++)
                    mma16816(acc[mt][ng], a[mt], bf[ng]);
        }
    }

    const int quad = lane >> 2, qt = lane & 3;
    #pragma unroll
    for (int mt = 0; mt < 2; mt++) {
        #pragma unroll
        for (int ng = 0; ng < 8; ng++) {
            int r0 = row0 + wm * 32 + mt * 16 + quad;
            int c  = col0 + wn * 64 + ng * 8 + qt * 2;
            #pragma unroll
            for (int h = 0; h < 2; h++) {
                size_t r = (size_t)(r0 + h * 8);
                float v0 = acc[mt][ng][h * 2 + 0];
                float v1 = acc[mt][ng][h * 2 + 1];
                if (epi == 2) {
                    float2 o;
                    o.x = __bfloat162float(__float2bfloat16(v0));
                    o.y = __bfloat162float(__float2bfloat16(v1));
                    *reinterpret_cast<float2*>((float*)C + r * N + c) = o;
                } else {
                    __nv_bfloat16 b0 = __float2bfloat16(v0);
                    __nv_bfloat16 b1 = __float2bfloat16(v1);
                    if (epi == 1) {
                        b0 = __float2bfloat16(fp8_round(__bfloat162float(b0)));
                        b1 = __float2bfloat16(fp8_round(__bfloat162float(b1)));
                    }
                    __nv_bfloat162 o = __halves2bfloat162(b0, b1);
                    *reinterpret_cast<__nv_bfloat162*>((__nv_bfloat16*)C + r * N + c) = o;
                }
            }
        }
    }
}

// ================= attention on mma.sync, cp.async-pipelined =================
#define SKA 136
#define AQ_BYTES  (128*SKA*2)   // 34816

__device__ __forceinline__ void tile_copy(__nv_bfloat16* dst, const __nv_bfloat16* src, int tid) {
    #pragma unroll
    for (int it = 0; it < 8; it++) {
        int idx = tid + it * 256;
        int r = idx >> 4, v = idx & 15;
        *reinterpret_cast<uint4*>(dst + r * SKA + v * 8) =
            *reinterpret_cast<const uint4*>(src + (size_t)r * DMODEL + v * 8);
    }
}
// async version: same layout, 8 cp.async per thread
__device__ __forceinline__ void tile_copy_async(uint32_t dstBase, const __nv_bfloat16* src, int tid) {
    #pragma unroll
    for (int it = 0; it < 8; it++) {
        int idx = tid + it * 256;
        int r = idx >> 4, v = idx & 15;
        cp_async16(dstBase + (r * SKA + v * 8) * 2, src + (size_t)r * DMODEL + v * 8);
    }
}

__device__ __forceinline__ void s_chunk_mma(float sacc[2][8][4],
                                            const uint32_t aB[2], const uint32_t bB[4],
                                            float scale_b) {
    #pragma unroll
    for (int mt = 0; mt < 2; mt++)
        #pragma unroll
        for (int ng = 0; ng < 8; ng++)
            #pragma unroll
            for (int e = 0; e < 4; e++) sacc[mt][ng][e] = 0.f;
    #pragma unroll
    for (int ks = 0; ks < 8; ks++) {
        uint32_t a[2][4];
        #pragma unroll
        for (int mt = 0; mt < 2; mt++)
            ldmatrix_x4(a[mt][0], a[mt][1], a[mt][2], a[mt][3], aB[mt] + ks * 32);
        uint32_t bf8[8][2];
        #pragma unroll
        for (int nt = 0; nt < 4; nt++) {
            uint32_t r0, r1, r2, r3;
            ldmatrix_x4(r0, r1, r2, r3, bB[nt] + ks * 32);
            bf8[nt * 2 + 0][0] = r0; bf8[nt * 2 + 0][1] = r2;
            bf8[nt * 2 + 1][0] = r1; bf8[nt * 2 + 1][1] = r3;
        }
        #pragma unroll
        for (int mt = 0; mt < 2; mt++)
            #pragma unroll
            for (int ng = 0; ng < 8; ng++)
                mma16816(sacc[mt][ng], a[mt], bf8[ng]);
    }
    #pragma unroll
    for (int mt = 0; mt < 2; mt++)
        #pragma unroll
        for (int ng = 0; ng < 8; ng++)
            #pragma unroll
            for (int e = 0; e < 4; e++) {
                float t = __bfloat162float(__float2bfloat16(sacc[mt][ng][e]));
                sacc[mt][ng][e] = __bfloat162float(__float2bfloat16(t * scale_b));
            }
}

// Pass A: exact per-row max / sumexp; double-buffered K with cp.async prefetch
// SMEM: sQ | sK0 | sK1 | pm pl mr lr  -> 3*AQ + 3072
__global__ __launch_bounds__(256) void k_attn_stats_mma()
{
    extern __shared__ __align__(16) char dynsm[];
    __nv_bfloat16* sQ = (__nv_bfloat16*)dynsm;
    float* pm = (float*)(dynsm + 3 * AQ_BYTES);            // [2][128]
    float* pl = (float*)(dynsm + 3 * AQ_BYTES + 1024);     // [2][128]
    float* mr = (float*)(dynsm + 3 * AQ_BYTES + 2048);     // [128]
    float* lr = (float*)(dynsm + 3 * AQ_BYTES + 2560);     // [128]

    const uint32_t smemBase = smem_u32(dynsm);
    const uint32_t sKbase = smemBase + AQ_BYTES;           // two K buffers

    const int tid = threadIdx.x, lane = tid & 31, wid = tid >> 5;
    const int wm = wid & 3, wn = wid >> 2;
    const int quad = lane >> 2, qt = lane & 3;
    const int qt0 = blockIdx.x, bh = blockIdx.y, b = bh >> 4, hh = bh & 15;
    const float scale_b = __bfloat162float(__float2bfloat16(0.08838834764831845f));

    const __nv_bfloat16* Qg = g_Q + ((size_t)(b * SEQ + qt0 * 128)) * DMODEL + hh * HDIM;
    const __nv_bfloat16* Kg = g_K + (size_t)(b * SEQ) * DMODEL + hh * HDIM;

    // prefetch K(0) async, load Q with regular stores in parallel
    tile_copy_async(sKbase, Kg, tid);
    CP_COMMIT();
    tile_copy(sQ, Qg, tid);
    if (tid < 128) { mr[tid] = -3.0e38f; lr[tid] = 0.f; }

    const int rsel = (lane & 7) + ((lane >> 3) & 1) * 8;
    const int csel = (lane >> 4) * 8;
    uint32_t aB[2], bOff[4];
    #pragma unroll
    for (int mt = 0; mt < 2; mt++)
        aB[mt] = smem_u32(sQ + (wm * 32 + mt * 16 + rsel) * SKA + csel);
    #pragma unroll
    for (int nt = 0; nt < 4; nt++)
        bOff[nt] = ((wn * 64 + nt * 16 + rsel) * SKA + csel) * 2;

    for (int kt = 0; kt < 16; kt++) {
        CP_WAIT0();
        __syncthreads();                                   // K(kt) ready
        if (kt < 15) {                                     // prefetch K(kt+1) into other buffer
            tile_copy_async(sKbase + ((kt + 1) & 1) * AQ_BYTES,
                            Kg + (size_t)((kt + 1) * 128) * DMODEL, tid);
            CP_COMMIT();
        }
        uint32_t bB[4];
        uint32_t bufOff = (kt & 1) * AQ_BYTES;
        #pragma unroll
        for (int nt = 0; nt < 4; nt++) bB[nt] = sKbase + bufOff + bOff[nt];
        float sacc[2][8][4];
        s_chunk_mma(sacc, aB, bB, scale_b);
        #pragma unroll
        for (int mt = 0; mt < 2; mt++)
            #pragma unroll
            for (int h = 0; h < 2; h++) {
                float cmax = -3.0e38f;
                #pragma unroll
                for (int ng = 0; ng < 8; ng++)
                    cmax = fmaxf(cmax, fmaxf(sacc[mt][ng][h*2], sacc[mt][ng][h*2+1]));
                cmax = fmaxf(cmax, __shfl_xor_sync(0xffffffffu, cmax, 1));
                cmax = fmaxf(cmax, __shfl_xor_sync(0xffffffffu, cmax, 2));
                float cl = 0.f;
                #pragma unroll
                for (int ng = 0; ng < 8; ng++)
                    cl += expf(sacc[mt][ng][h*2] - cmax) + expf(sacc[mt][ng][h*2+1] - cmax);
                cl += __shfl_xor_sync(0xffffffffu, cl, 1);
                cl += __shfl_xor_sync(0xffffffffu, cl, 2);
                if (qt == 0) {
                    int row = wm * 32 + mt * 16 + quad + h * 8;
                    pm[wn * 128 + row] = cmax;
                    pl[wn * 128 + row] = cl;
                }
            }
        __syncthreads();
        if (tid < 128) {
            float m0 = pm[tid], m1 = pm[128 + tid];
            float l0 = pl[tid], l1 = pl[128 + tid];
            float cm = fmaxf(m0, m1);
            float cl = l0 * expf(m0 - cm) + l1 * expf(m1 - cm);
            float mo = mr[tid], lo = lr[tid];
            float mn = fmaxf(mo, cm);
            lr[tid] = lo * expf(mo - mn) + cl * expf(cm - mn);
            mr[tid] = mn;
        }
    }
    __syncthreads();
    if (tid < 128) {
        g_m[(size_t)bh * SEQ + qt0 * 128 + tid] = mr[tid];
        g_l[(size_t)bh * SEQ + qt0 * 128 + tid] = lr[tid];
    }
}

// Pass B: recompute S, quantize P to e4m3, O = P @ V
// Separate K/V/P buffers; V streams during S+quant, next K streams during PV.
// SMEM: sQ | sK | sV | sP | sm sl  -> 4*AQ + 1024
__global__ __launch_bounds__(256) void k_attn_av_mma()
{
    extern __shared__ __align__(16) char dynsm[];
    __nv_bfloat16* sQ  = (__nv_bfloat16*)dynsm;
    __nv_bfloat16* sK  = (__nv_bfloat16*)(dynsm + AQ_BYTES);
    __nv_bfloat16* sV  = (__nv_bfloat16*)(dynsm + 2 * AQ_BYTES);
    __nv_bfloat16* sP  = (__nv_bfloat16*)(dynsm + 3 * AQ_BYTES);
    float* sm = (float*)(dynsm + 4 * AQ_BYTES);            // [128]
    float* sl = (float*)(dynsm + 4 * AQ_BYTES + 512);      // [128]

    const uint32_t sKu = smem_u32(sK), sVu = smem_u32(sV);

    const int tid = threadIdx.x, lane = tid & 31, wid = tid >> 5;
    const int wm = wid & 3, wn = wid >> 2;
    const int quad = lane >> 2, qt = lane & 3;
    const int qt0 = blockIdx.x, bh = blockIdx.y, b = bh >> 4, hh = bh & 15;
    const float scale_b = __bfloat162float(__float2bfloat16(0.08838834764831845f));

    const __nv_bfloat16* Qg = g_Q + ((size_t)(b * SEQ + qt0 * 128)) * DMODEL + hh * HDIM;
    const __nv_bfloat16* Kg = g_K + (size_t)(b * SEQ) * DMODEL + hh * HDIM;
    const __nv_bfloat16* Vg = g_V + (size_t)(b * SEQ) * DMODEL + hh * HDIM;

    // prefetch K(0) async; load Q + stats with regular stores meanwhile
    tile_copy_async(sKu, Kg, tid);
    CP_COMMIT();
    tile_copy(sQ, Qg, tid);
    if (tid < 128) {
        sm[tid] = g_m[(size_t)bh * SEQ + qt0 * 128 + tid];
        sl[tid] = g_l[(size_t)bh * SEQ + qt0 * 128 + tid];
    }
    __syncthreads();

    float mrow[2][2], lrow[2][2];
    #pragma unroll
    for (int mt = 0; mt < 2; mt++)
        #pragma unroll
        for (int h = 0; h < 2; h++) {
            int row = wm * 32 + mt * 16 + quad + h * 8;
            mrow[mt][h] = sm[row];
            lrow[mt][h] = sl[row];
        }

    const int rsel = (lane & 7) + ((lane >> 3) & 1) * 8;
    const int csel = (lane >> 4) * 8;
    const int rselT = (lane & 7) + ((lane >> 4) & 1) * 8;   // V-trans selectors
    const int cselT = ((lane >> 3) & 1) * 8;
    uint32_t aB[2], bB[4], pB[2], vB[4];
    #pragma unroll
    for (int mt = 0; mt < 2; mt++) {
        aB[mt] = smem_u32(sQ + (wm * 32 + mt * 16 + rsel) * SKA + csel);
        pB[mt] = smem_u32(sP + (wm * 32 + mt * 16 + rsel) * SKA + csel);
    }
    #pragma unroll
    for (int nt = 0; nt < 4; nt++) {
        bB[nt] = smem_u32(sK + (wn * 64 + nt * 16 + rsel) * SKA + csel);
        vB[nt] = smem_u32(sV + rselT * SKA + wn * 64 + nt * 16 + cselT);
    }

    float oacc[2][8][4] = {};

    for (int kt = 0; kt < 16; kt++) {
        CP_WAIT0();
        __syncthreads();                     // K(kt) landed; prior PV done with sV/sP
        tile_copy_async(sVu, Vg + (size_t)(kt * 128) * DMODEL, tid);   // V streams now
        CP_COMMIT();
        float sacc[2][8][4];
        s_chunk_mma(sacc, aB, bB, scale_b);
        #pragma unroll
        for (int mt = 0; mt < 2; mt++)
            #pragma unroll
            for (int ng = 0; ng < 8; ng++)
                #pragma unroll
                for (int h = 0; h < 2; h++) {
                    float p0 = expf(sacc[mt][ng][h*2]   - mrow[mt][h]) / lrow[mt][h];
                    float p1 = expf(sacc[mt][ng][h*2+1] - mrow[mt][h]) / lrow[mt][h];
                    __nv_bfloat162 pq = __halves2bfloat162(
                        __float2bfloat16(fp8_round_bf(p0)),
                        __float2bfloat16(fp8_round_bf(p1)));
                    int row = wm * 32 + mt * 16 + quad + h * 8;
                    int col = wn * 64 + ng * 8 + qt * 2;
                    *reinterpret_cast<__nv_bfloat162*>(sP + row * SKA + col) = pq;
                }
        CP_WAIT0();
        __syncthreads();                     // V(kt) landed; P visible; sK reads done
        if (kt < 15) {                       // next K streams during PV compute
            tile_copy_async(sKu, Kg + (size_t)((kt + 1) * 128) * DMODEL, tid);
            CP_COMMIT();
        }
        #pragma unroll
        for (int ks = 0; ks < 8; ks++) {
            uint32_t a[2][4];
            #pragma unroll
            for (int mt = 0; mt < 2; mt++)
                ldmatrix_x4(a[mt][0], a[mt][1], a[mt][2], a[mt][3], pB[mt] + ks * 32);
            uint32_t bf8[8][2];
            #pragma unroll
            for (int nt = 0; nt < 4; nt++) {
                uint32_t r0, r1, r2, r3;
                ldmatrix_x4_trans(r0, r1, r2, r3, vB[nt] + ks * 16 * SKA * 2);
                bf8[nt * 2 + 0][0] = r0; bf8[nt * 2 + 0][1] = r2;
                bf8[nt * 2 + 1][0] = r1; bf8[nt * 2 + 1][1] = r3;
            }
            #pragma unroll
            for (int mt = 0; mt < 2; mt++)
                #pragma unroll
                for (int ng = 0; ng < 8; ng++)
                    mma16816(oacc[mt][ng], a[mt], bf8[ng]);
        }
    }

    #pragma unroll
    for (int mt = 0; mt < 2; mt++)
        #pragma unroll
        for (int ng = 0; ng < 8; ng++)
            #pragma unroll
            for (int h = 0; h < 2; h++) {
                int row = qt0 * 128 + wm * 32 + mt * 16 + quad + h * 8;
                int col = wn * 64 + ng * 8 + qt * 2;
                __nv_bfloat162 o = __halves2bfloat162(
                    __float2bfloat16(fp8_round_bf(oacc[mt][ng][h*2])),
                    __float2bfloat16(fp8_round_bf(oacc[mt][ng][h*2+1])));
                *reinterpret_cast<__nv_bfloat162*>(
                    g_AO + (size_t)(b * SEQ + row) * DMODEL + hh * HDIM + col) = o;
            }
}

// ---------------- launch ----------------
extern "C" void kernel_launch(void* const* d_in, const int* in_sizes, int n_in,
                              void* d_out, int out_size)
{
    int iq, ikv, iwq, iwk, iwv, iwo;
    if (in_sizes[0] == NACT) {           // signature / insertion order
        iq = 0; ikv = 1; iwq = 2; iwk = 3; iwv = 4; iwo = 5;
    } else {                             // alphabetically sorted keys
        iwk = 0; iwo = 1; iwq = 2; iwv = 3; ikv = 4; iq = 5;
    }
    const float* in_q  = (const float*)d_in[iq];
    const float* in_kv = (const float*)d_in[ikv];
    const float* wq = (const float*)d_in[iwq];
    const float* wk = (const float*)d_in[iwk];
    const float* wv = (const float*)d_in[iwv];
    const float* wo = (const float*)d_in[iwo];

    __nv_bfloat16 *xq, *xkv, *wqe, *wke, *wve, *woe, *q, *k, *v, *ao;
    cudaGetSymbolAddress((void**)&xq,  g_Xq);
    cudaGetSymbolAddress((void**)&xkv, g_Xkv);
    cudaGetSymbolAddress((void**)&wqe, g_Wq);
    cudaGetSymbolAddress((void**)&wke, g_Wk);
    cudaGetSymbolAddress((void**)&wve, g_Wv);
    cudaGetSymbolAddress((void**)&woe, g_Wo);
    cudaGetSymbolAddress((void**)&q,   g_Q);
    cudaGetSymbolAddress((void**)&k,   g_K);
    cudaGetSymbolAddress((void**)&v,   g_V);
    cudaGetSymbolAddress((void**)&ao,  g_AO);

    // opt-in dynamic SMEM (idempotent host calls)
    const int SMEM_A = 3 * AQ_BYTES + 3072;       // 107520
    const int SMEM_B = 4 * AQ_BYTES + 1024;       // 140288
    cudaFuncSetAttribute(k_gemm_mma,       cudaFuncAttributeMaxDynamicSharedMemorySize, GSMEM);
    cudaFuncSetAttribute(k_attn_stats_mma, cudaFuncAttributeMaxDynamicSharedMemorySize, SMEM_A);
    cudaFuncSetAttribute(k_attn_av_mma,    cudaFuncAttributeMaxDynamicSharedMemorySize, SMEM_B);

    // quantize activations; transpose+quantize weights (mma B operand is [N,K])
    k_quant_f32<<<NACT / 256, 256>>>(in_q,  xq,  NACT);
    k_quant_f32<<<NACT / 256, 256>>>(in_kv, xkv, NACT);
    dim3 gt(DMODEL / 32, DMODEL / 32);
    k_wtrans<<<gt, 1024>>>(wq, wqe);
    k_wtrans<<<gt, 1024>>>(wk, wke);
    k_wtrans<<<gt, 1024>>>(wv, wve);
    k_wtrans<<<gt, 1024>>>(wo, woe);

    // projections on tensor cores (V fuses e4m3 re-quant into epilogue)
    dim3 gg(DMODEL / TBN, MROWS / TBM);
    k_gemm_mma<<<gg, 256, GSMEM>>>(xq,  wqe, q, MROWS, DMODEL, DMODEL, 0);
    k_gemm_mma<<<gg, 256, GSMEM>>>(xkv, wke, k, MROWS, DMODEL, DMODEL, 0);
    k_gemm_mma<<<gg, 256, GSMEM>>>(xkv, wve, v, MROWS, DMODEL, DMODEL, 1);

    // attention on tensor cores: stats pass then AV pass (cp.async pipelined)
    dim3 ga(SEQ / 128, BATCH * NHEAD);
    k_attn_stats_mma<<<ga, 256, SMEM_A>>>();
    k_attn_av_mma<<<ga, 256, SMEM_B>>>();

    // output projection: bf16-rounded values widened to FLOAT32 output buffer
    k_gemm_mma<<<gg, 256, GSMEM>>>(ao, woe, d_out, MROWS, DMODEL, DMODEL, 2);
}

// round 17
// speedup vs baseline: 11.9591x; 1.1602x over previous
#include <cuda_runtime.h>
#include <cuda_bf16.h>
#include <cuda_fp8.h>
#include <cstdint>
#include <cstddef>

// Problem shape (fixed by the dataset)
#define BATCH  2
#define SEQ    2048
#define DMODEL 2048
#define NHEAD  16
#define HDIM   128
#define MROWS  (BATCH*SEQ)       // 4096
#define NACT   (MROWS*DMODEL)    // 8388608
#define NWEI   (DMODEL*DMODEL)   // 4194304

// ---------------- scratch: __device__ globals (no dynamic allocation) ----------
__device__ __nv_bfloat16 g_Xq [NACT];
__device__ __nv_bfloat16 g_Xkv[NACT];
__device__ __nv_bfloat16 g_Wq [NWEI];   // TRANSPOSED [n][k], e4m3-rounded bf16
__device__ __nv_bfloat16 g_Wk [NWEI];
__device__ __nv_bfloat16 g_Wv [NWEI];
__device__ __nv_bfloat16 g_Wo [NWEI];
__device__ __nv_bfloat16 g_Q  [NACT];
__device__ __nv_bfloat16 g_K  [NACT];
__device__ __nv_bfloat16 g_V  [NACT];
__device__ __nv_bfloat16 g_AO [NACT];
__device__ float g_m[BATCH*NHEAD*SEQ];
__device__ float g_l[BATCH*NHEAD*SEQ];

// ---------------- small helpers ----------------
__device__ __forceinline__ uint32_t smem_u32(const void* p) {
    uint32_t a;
    asm("{ .reg .u64 t; cvta.to.shared.u64 t, %1; cvt.u32.u64 %0, t; }" : "=r"(a) : "l"(p));
    return a;
}
__device__ __forceinline__ void ldmatrix_x4(uint32_t& r0, uint32_t& r1,
                                            uint32_t& r2, uint32_t& r3, uint32_t addr) {
    asm volatile("ldmatrix.sync.aligned.m8n8.x4.shared.b16 {%0,%1,%2,%3}, [%4];"
                 : "=r"(r0), "=r"(r1), "=r"(r2), "=r"(r3) : "r"(addr));
}
__device__ __forceinline__ void ldmatrix_x4_trans(uint32_t& r0, uint32_t& r1,
                                                  uint32_t& r2, uint32_t& r3, uint32_t addr) {
    asm volatile("ldmatrix.sync.aligned.m8n8.x4.trans.shared.b16 {%0,%1,%2,%3}, [%4];"
                 : "=r"(r0), "=r"(r1), "=r"(r2), "=r"(r3) : "r"(addr));
}
__device__ __forceinline__ void mma16816(float* c, const uint32_t* a, const uint32_t* b) {
    asm volatile(
        "mma.sync.aligned.m16n8k16.row.col.f32.bf16.bf16.f32 "
        "{%0,%1,%2,%3}, {%4,%5,%6,%7}, {%8,%9}, {%0,%1,%2,%3};"
        : "+f"(c[0]), "+f"(c[1]), "+f"(c[2]), "+f"(c[3])
        : "r"(a[0]), "r"(a[1]), "r"(a[2]), "r"(a[3]), "r"(b[0]), "r"(b[1]));
}
__device__ __forceinline__ void cp_async16(uint32_t saddr, const void* gaddr) {
    asm volatile("cp.async.cg.shared.global [%0], [%1], 16;" :: "r"(saddr), "l"(gaddr));
}
#define CP_COMMIT() asm volatile("cp.async.commit_group;" ::: "memory")
#define CP_WAIT0()  asm volatile("cp.async.wait_group 0;" ::: "memory")
#define CP_WAIT1()  asm volatile("cp.async.wait_group 1;" ::: "memory")

// ---------------- fp8 helpers ----------------
__device__ __forceinline__ float fp8_round(float x) {
    __nv_fp8_storage_t r = __nv_cvt_float_to_fp8(x, __NV_SATFINITE, __NV_E4M3);
    __half_raw hr = __nv_cvt_fp8_to_halfraw(r, __NV_E4M3);
    return __half2float(__half(hr));
}
__device__ __forceinline__ float fp8_round_bf(float x) {
    float xb = __bfloat162float(__float2bfloat16(x));
    return fp8_round(xb);
}

// ---------------- quantize / transpose kernels ----------------
__global__ void k_quant_f32(const float* __restrict__ in, __nv_bfloat16* __restrict__ out, int n) {
    int i = blockIdx.x * blockDim.x + threadIdx.x;
    if (i < n) out[i] = __float2bfloat16(fp8_round(in[i]));
}
__global__ __launch_bounds__(1024) void k_wtrans(const float* __restrict__ W,
                                                 __nv_bfloat16* __restrict__ Wt) {
    __shared__ float t[32][33];
    int tx = threadIdx.x & 31, ty = threadIdx.x >> 5;
    int n0 = blockIdx.x * 32, k0 = blockIdx.y * 32;
    t[ty][tx] = W[(size_t)(k0 + ty) * DMODEL + n0 + tx];
    __syncthreads();
    Wt[(size_t)(n0 + ty) * DMODEL + k0 + tx] = __float2bfloat16(fp8_round(t[tx][ty]));
}

// ---------------- mma.sync dense GEMM: 3-stage cp.async pipeline ----------------
#define TBM 128
#define TBN 128
#define TBK 32
#define SKP 40
#define GTILE (TBM*SKP*2)
#define GSTG  (2*GTILE)
#define GSMEM (3*GSTG)
__global__ __launch_bounds__(256, 2) void k_gemm_mma(const __nv_bfloat16* __restrict__ A,
                                                     const __nv_bfloat16* __restrict__ Bt,
                                                     void* __restrict__ C,
                                                     int M, int N, int K, int epi)
{
    extern __shared__ __align__(16) char gsm[];
    const uint32_t smemBase = smem_u32(gsm);
    const int tid = threadIdx.x, wid = tid >> 5, lane = tid & 31;
    const int wm = wid & 3, wn = wid >> 2;
    const int row0 = blockIdx.y * TBM, col0 = blockIdx.x * TBN;
    const int rsel = (lane & 7) + ((lane >> 3) & 1) * 8;
    const int csel = (lane >> 4) * 8;

    uint32_t aOff[2], bOff[4];
    #pragma unroll
    for (int mt = 0; mt < 2; mt++)
        aOff[mt] = ((wm * 32 + mt * 16 + rsel) * SKP + csel) * 2;
    #pragma unroll
    for (int nt = 0; nt < 4; nt++)
        bOff[nt] = GTILE + ((wn * 64 + nt * 16 + rsel) * SKP + csel) * 2;

    const int lr0 = tid >> 2, lcg = (tid & 3) * 8;
    const int lr1 = lr0 + 64;
    const int nch = K / TBK;

    auto issue = [&](int ch, int stg) {
        uint32_t sA = smemBase + stg * GSTG;
        uint32_t sB = sA + GTILE;
        int kk = ch * TBK;
        cp_async16(sA + (lr0 * SKP + lcg) * 2, A  + (size_t)(row0 + lr0) * K + kk + lcg);
        cp_async16(sA + (lr1 * SKP + lcg) * 2, A  + (size_t)(row0 + lr1) * K + kk + lcg);
        cp_async16(sB + (lr0 * SKP + lcg) * 2, Bt + (size_t)(col0 + lr0) * K + kk + lcg);
        cp_async16(sB + (lr1 * SKP + lcg) * 2, Bt + (size_t)(col0 + lr1) * K + kk + lcg);
        CP_COMMIT();
    };

    float acc[2][8][4] = {};

    issue(0, 0);
    issue(1, 1);
    for (int i = 0; i < nch; i++) {
        if (i < nch - 1) CP_WAIT1();
        else             CP_WAIT0();
        __syncthreads();
        if (i + 2 < nch) issue(i + 2, (i + 2) % 3);
        uint32_t sbase = smemBase + (i % 3) * GSTG;
        #pragma unroll
        for (int ks = 0; ks < 2; ks++) {
            uint32_t a[2][4];
            #pragma unroll
            for (int mt = 0; mt < 2; mt++)
                ldmatrix_x4(a[mt][0], a[mt][1], a[mt][2], a[mt][3], sbase + aOff[mt] + ks * 32);
            uint32_t bf[8][2];
            #pragma unroll
            for (int nt = 0; nt < 4; nt++) {
                uint32_t r0, r1, r2, r3;
                ldmatrix_x4(r0, r1, r2, r3, sbase + bOff[nt] + ks * 32);
                bf[nt * 2 + 0][0] = r0; bf[nt * 2 + 0][1] = r2;
                bf[nt * 2 + 1][0] = r1; bf[nt * 2 + 1][1] = r3;
            }
            #pragma unroll
            for (int mt = 0; mt < 2; mt++)
                #pragma unroll
                for (int ng = 0; ng < 8; ng++)
                    mma16816(acc[mt][ng], a[mt], bf[ng]);
        }
    }

    const int quad = lane >> 2, qt = lane & 3;
    #pragma unroll
    for (int mt = 0; mt < 2; mt++) {
        #pragma unroll
        for (int ng = 0; ng < 8; ng++) {
            int r0 = row0 + wm * 32 + mt * 16 + quad;
            int c  = col0 + wn * 64 + ng * 8 + qt * 2;
            #pragma unroll
            for (int h = 0; h < 2; h++) {
                size_t r = (size_t)(r0 + h * 8);
                float v0 = acc[mt][ng][h * 2 + 0];
                float v1 = acc[mt][ng][h * 2 + 1];
                if (epi == 2) {
                    float2 o;
                    o.x = __bfloat162float(__float2bfloat16(v0));
                    o.y = __bfloat162float(__float2bfloat16(v1));
                    *reinterpret_cast<float2*>((float*)C + r * N + c) = o;
                } else {
                    __nv_bfloat16 b0 = __float2bfloat16(v0);
                    __nv_bfloat16 b1 = __float2bfloat16(v1);
                    if (epi == 1) {
                        b0 = __float2bfloat16(fp8_round(__bfloat162float(b0)));
                        b1 = __float2bfloat16(fp8_round(__bfloat162float(b1)));
                    }
                    __nv_bfloat162 o = __halves2bfloat162(b0, b1);
                    *reinterpret_cast<__nv_bfloat162*>((__nv_bfloat16*)C + r * N + c) = o;
                }
            }
        }
    }
}

// ================= attention on mma.sync, cp.async-pipelined =================
#define SKA 136
#define AQ_BYTES  (128*SKA*2)   // 34816

__device__ __forceinline__ void tile_copy(__nv_bfloat16* dst, const __nv_bfloat16* src, int tid) {
    #pragma unroll
    for (int it = 0; it < 8; it++) {
        int idx = tid + it * 256;
        int r = idx >> 4, v = idx & 15;
        *reinterpret_cast<uint4*>(dst + r * SKA + v * 8) =
            *reinterpret_cast<const uint4*>(src + (size_t)r * DMODEL + v * 8);
    }
}
__device__ __forceinline__ void tile_copy_async(uint32_t dstBase, const __nv_bfloat16* src, int tid) {
    #pragma unroll
    for (int it = 0; it < 8; it++) {
        int idx = tid + it * 256;
        int r = idx >> 4, v = idx & 15;
        cp_async16(dstBase + (r * SKA + v * 8) * 2, src + (size_t)r * DMODEL + v * 8);
    }
}

__device__ __forceinline__ void s_chunk_mma(float sacc[2][8][4],
                                            const uint32_t aB[2], const uint32_t bB[4],
                                            float scale_b) {
    #pragma unroll
    for (int mt = 0; mt < 2; mt++)
        #pragma unroll
        for (int ng = 0; ng < 8; ng++)
            #pragma unroll
            for (int e = 0; e < 4; e++) sacc[mt][ng][e] = 0.f;
    #pragma unroll
    for (int ks = 0; ks < 8; ks++) {
        uint32_t a[2][4];
        #pragma unroll
        for (int mt = 0; mt < 2; mt++)
            ldmatrix_x4(a[mt][0], a[mt][1], a[mt][2], a[mt][3], aB[mt] + ks * 32);
        uint32_t bf8[8][2];
        #pragma unroll
        for (int nt = 0; nt < 4; nt++) {
            uint32_t r0, r1, r2, r3;
            ldmatrix_x4(r0, r1, r2, r3, bB[nt] + ks * 32);
            bf8[nt * 2 + 0][0] = r0; bf8[nt * 2 + 0][1] = r2;
            bf8[nt * 2 + 1][0] = r1; bf8[nt * 2 + 1][1] = r3;
        }
        #pragma unroll
        for (int mt = 0; mt < 2; mt++)
            #pragma unroll
            for (int ng = 0; ng < 8; ng++)
                mma16816(sacc[mt][ng], a[mt], bf8[ng]);
    }
    #pragma unroll
    for (int mt = 0; mt < 2; mt++)
        #pragma unroll
        for (int ng = 0; ng < 8; ng++)
            #pragma unroll
            for (int e = 0; e < 4; e++) {
                float t = __bfloat162float(__float2bfloat16(sacc[mt][ng][e]));
                sacc[mt][ng][e] = __bfloat162float(__float2bfloat16(t * scale_b));
            }
}

// Pass A: per-row max / sumexp; fast __expf (result feeds e4m3-quantized P,
// so ~1e-6 relative exp error is invisible after quantization)
__global__ __launch_bounds__(256) void k_attn_stats_mma()
{
    extern __shared__ __align__(16) char dynsm[];
    __nv_bfloat16* sQ = (__nv_bfloat16*)dynsm;
    float* pm = (float*)(dynsm + 3 * AQ_BYTES);            // [2][128]
    float* pl = (float*)(dynsm + 3 * AQ_BYTES + 1024);     // [2][128]
    float* mr = (float*)(dynsm + 3 * AQ_BYTES + 2048);     // [128]
    float* lr = (float*)(dynsm + 3 * AQ_BYTES + 2560);     // [128]

    const uint32_t smemBase = smem_u32(dynsm);
    const uint32_t sKbase = smemBase + AQ_BYTES;           // two K buffers

    const int tid = threadIdx.x, lane = tid & 31, wid = tid >> 5;
    const int wm = wid & 3, wn = wid >> 2;
    const int quad = lane >> 2, qt = lane & 3;
    const int qt0 = blockIdx.x, bh = blockIdx.y, b = bh >> 4, hh = bh & 15;
    const float scale_b = __bfloat162float(__float2bfloat16(0.08838834764831845f));

    const __nv_bfloat16* Qg = g_Q + ((size_t)(b * SEQ + qt0 * 128)) * DMODEL + hh * HDIM;
    const __nv_bfloat16* Kg = g_K + (size_t)(b * SEQ) * DMODEL + hh * HDIM;

    tile_copy_async(sKbase, Kg, tid);
    CP_COMMIT();
    tile_copy(sQ, Qg, tid);
    if (tid < 128) { mr[tid] = -3.0e38f; lr[tid] = 0.f; }

    const int rsel = (lane & 7) + ((lane >> 3) & 1) * 8;
    const int csel = (lane >> 4) * 8;
    uint32_t aB[2], bOff[4];
    #pragma unroll
    for (int mt = 0; mt < 2; mt++)
        aB[mt] = smem_u32(sQ + (wm * 32 + mt * 16 + rsel) * SKA + csel);
    #pragma unroll
    for (int nt = 0; nt < 4; nt++)
        bOff[nt] = ((wn * 64 + nt * 16 + rsel) * SKA + csel) * 2;

    for (int kt = 0; kt < 16; kt++) {
        CP_WAIT0();
        __syncthreads();
        if (kt < 15) {
            tile_copy_async(sKbase + ((kt + 1) & 1) * AQ_BYTES,
                            Kg + (size_t)((kt + 1) * 128) * DMODEL, tid);
            CP_COMMIT();
        }
        uint32_t bB[4];
        uint32_t bufOff = (kt & 1) * AQ_BYTES;
        #pragma unroll
        for (int nt = 0; nt < 4; nt++) bB[nt] = sKbase + bufOff + bOff[nt];
        float sacc[2][8][4];
        s_chunk_mma(sacc, aB, bB, scale_b);
        #pragma unroll
        for (int mt = 0; mt < 2; mt++)
            #pragma unroll
            for (int h = 0; h < 2; h++) {
                float cmax = -3.0e38f;
                #pragma unroll
                for (int ng = 0; ng < 8; ng++)
                    cmax = fmaxf(cmax, fmaxf(sacc[mt][ng][h*2], sacc[mt][ng][h*2+1]));
                cmax = fmaxf(cmax, __shfl_xor_sync(0xffffffffu, cmax, 1));
                cmax = fmaxf(cmax, __shfl_xor_sync(0xffffffffu, cmax, 2));
                float cl = 0.f;
                #pragma unroll
                for (int ng = 0; ng < 8; ng++)
                    cl += __expf(sacc[mt][ng][h*2] - cmax) + __expf(sacc[mt][ng][h*2+1] - cmax);
                cl += __shfl_xor_sync(0xffffffffu, cl, 1);
                cl += __shfl_xor_sync(0xffffffffu, cl, 2);
                if (qt == 0) {
                    int row = wm * 32 + mt * 16 + quad + h * 8;
                    pm[wn * 128 + row] = cmax;
                    pl[wn * 128 + row] = cl;
                }
            }
        __syncthreads();
        if (tid < 128) {
            float m0 = pm[tid], m1 = pm[128 + tid];
            float l0 = pl[tid], l1 = pl[128 + tid];
            float cm = fmaxf(m0, m1);
            float cl = l0 * __expf(m0 - cm) + l1 * __expf(m1 - cm);
            float mo = mr[tid], lo = lr[tid];
            float mn = fmaxf(mo, cm);
            lr[tid] = lo * __expf(mo - mn) + cl * __expf(cm - mn);
            mr[tid] = mn;
        }
    }
    __syncthreads();
    if (tid < 128) {
        g_m[(size_t)bh * SEQ + qt0 * 128 + tid] = mr[tid];
        g_l[(size_t)bh * SEQ + qt0 * 128 + tid] = lr[tid];
    }
}

// Pass B: recompute S, quantize P to e4m3 (fast __expf + reciprocal), O = P @ V
__global__ __launch_bounds__(256) void k_attn_av_mma()
{
    extern __shared__ __align__(16) char dynsm[];
    __nv_bfloat16* sQ  = (__nv_bfloat16*)dynsm;
    __nv_bfloat16* sK  = (__nv_bfloat16*)(dynsm + AQ_BYTES);
    __nv_bfloat16* sV  = (__nv_bfloat16*)(dynsm + 2 * AQ_BYTES);
    __nv_bfloat16* sP  = (__nv_bfloat16*)(dynsm + 3 * AQ_BYTES);
    float* sm = (float*)(dynsm + 4 * AQ_BYTES);            // [128]
    float* sl = (float*)(dynsm + 4 * AQ_BYTES + 512);      // [128]

    const uint32_t sKu = smem_u32(sK), sVu = smem_u32(sV);

    const int tid = threadIdx.x, lane = tid & 31, wid = tid >> 5;
    const int wm = wid & 3, wn = wid >> 2;
    const int quad = lane >> 2, qt = lane & 3;
    const int qt0 = blockIdx.x, bh = blockIdx.y, b = bh >> 4, hh = bh & 15;
    const float scale_b = __bfloat162float(__float2bfloat16(0.08838834764831845f));

    const __nv_bfloat16* Qg = g_Q + ((size_t)(b * SEQ + qt0 * 128)) * DMODEL + hh * HDIM;
    const __nv_bfloat16* Kg = g_K + (size_t)(b * SEQ) * DMODEL + hh * HDIM;
    const __nv_bfloat16* Vg = g_V + (size_t)(b * SEQ) * DMODEL + hh * HDIM;

    tile_copy_async(sKu, Kg, tid);
    CP_COMMIT();
    tile_copy(sQ, Qg, tid);
    if (tid < 128) {
        sm[tid] = g_m[(size_t)bh * SEQ + qt0 * 128 + tid];
        sl[tid] = g_l[(size_t)bh * SEQ + qt0 * 128 + tid];
    }
    __syncthreads();

    float mrow[2][2], linv[2][2];
    #pragma unroll
    for (int mt = 0; mt < 2; mt++)
        #pragma unroll
        for (int h = 0; h < 2; h++) {
            int row = wm * 32 + mt * 16 + quad + h * 8;
            mrow[mt][h] = sm[row];
            linv[mt][h] = 1.0f / sl[row];    // hoisted reciprocal (1-ulp vs div each time)
        }

    const int rsel = (lane & 7) + ((lane >> 3) & 1) * 8;
    const int csel = (lane >> 4) * 8;
    const int rselT = (lane & 7) + ((lane >> 4) & 1) * 8;   // V-trans selectors
    const int cselT = ((lane >> 3) & 1) * 8;
    uint32_t aB[2], bB[4], pB[2], vB[4];
    #pragma unroll
    for (int mt = 0; mt < 2; mt++) {
        aB[mt] = smem_u32(sQ + (wm * 32 + mt * 16 + rsel) * SKA + csel);
        pB[mt] = smem_u32(sP + (wm * 32 + mt * 16 + rsel) * SKA + csel);
    }
    #pragma unroll
    for (int nt = 0; nt < 4; nt++) {
        bB[nt] = smem_u32(sK + (wn * 64 + nt * 16 + rsel) * SKA + csel);
        vB[nt] = smem_u32(sV + rselT * SKA + wn * 64 + nt * 16 + cselT);
    }

    float oacc[2][8][4] = {};

    for (int kt = 0; kt < 16; kt++) {
        CP_WAIT0();
        __syncthreads();                     // K(kt) landed; prior PV done with sV/sP
        tile_copy_async(sVu, Vg + (size_t)(kt * 128) * DMODEL, tid);   // V streams now
        CP_COMMIT();
        float sacc[2][8][4];
        s_chunk_mma(sacc, aB, bB, scale_b);
        #pragma unroll
        for (int mt = 0; mt < 2; mt++)
            #pragma unroll
            for (int ng = 0; ng < 8; ng++)
                #pragma unroll
                for (int h = 0; h < 2; h++) {
                    float p0 = __expf(sacc[mt][ng][h*2]   - mrow[mt][h]) * linv[mt][h];
                    float p1 = __expf(sacc[mt][ng][h*2+1] - mrow[mt][h]) * linv[mt][h];
                    __nv_bfloat162 pq = __halves2bfloat162(
                        __float2bfloat16(fp8_round_bf(p0)),
                        __float2bfloat16(fp8_round_bf(p1)));
                    int row = wm * 32 + mt * 16 + quad + h * 8;
                    int col = wn * 64 + ng * 8 + qt * 2;
                    *reinterpret_cast<__nv_bfloat162*>(sP + row * SKA + col) = pq;
                }
        CP_WAIT0();
        __syncthreads();                     // V(kt) landed; P visible; sK reads done
        if (kt < 15) {
            tile_copy_async(sKu, Kg + (size_t)((kt + 1) * 128) * DMODEL, tid);
            CP_COMMIT();
        }
        #pragma unroll
        for (int ks = 0; ks < 8; ks++) {
            uint32_t a[2][4];
            #pragma unroll
            for (int mt = 0; mt < 2; mt++)
                ldmatrix_x4(a[mt][0], a[mt][1], a[mt][2], a[mt][3], pB[mt] + ks * 32);
            uint32_t bf8[8][2];
            #pragma unroll
            for (int nt = 0; nt < 4; nt++) {
                uint32_t r0, r1, r2, r3;
                ldmatrix_x4_trans(r0, r1, r2, r3, vB[nt] + ks * 16 * SKA * 2);
                bf8[nt * 2 + 0][0] = r0; bf8[nt * 2 + 0][1] = r2;
                bf8[nt * 2 + 1][0] = r1; bf8[nt * 2 + 1][1] = r3;
            }
            #pragma unroll
            for (int mt = 0; mt < 2; mt++)
                #pragma unroll
                for (int ng = 0; ng < 8; ng++)
                    mma16816(oacc[mt][ng], a[mt], bf8[ng]);
        }
    }

    #pragma unroll
    for (int mt = 0; mt < 2; mt++)
        #pragma unroll
        for (int ng = 0; ng < 8; ng++)
            #pragma unroll
            for (int h = 0; h < 2; h++) {
                int row = qt0 * 128 + wm * 32 + mt * 16 + quad + h * 8;
                int col = wn * 64 + ng * 8 + qt * 2;
                __nv_bfloat162 o = __halves2bfloat162(
                    __float2bfloat16(fp8_round_bf(oacc[mt][ng][h*2])),
                    __float2bfloat16(fp8_round_bf(oacc[mt][ng][h*2+1])));
                *reinterpret_cast<__nv_bfloat162*>(
                    g_AO + (size_t)(b * SEQ + row) * DMODEL + hh * HDIM + col) = o;
            }
}

// ---------------- launch ----------------
extern "C" void kernel_launch(void* const* d_in, const int* in_sizes, int n_in,
                              void* d_out, int out_size)
{
    int iq, ikv, iwq, iwk, iwv, iwo;
    if (in_sizes[0] == NACT) {           // signature / insertion order
        iq = 0; ikv = 1; iwq = 2; iwk = 3; iwv = 4; iwo = 5;
    } else {                             // alphabetically sorted keys
        iwk = 0; iwo = 1; iwq = 2; iwv = 3; ikv = 4; iq = 5;
    }
    const float* in_q  = (const float*)d_in[iq];
    const float* in_kv = (const float*)d_in[ikv];
    const float* wq = (const float*)d_in[iwq];
    const float* wk = (const float*)d_in[iwk];
    const float* wv = (const float*)d_in[iwv];
    const float* wo = (const float*)d_in[iwo];

    __nv_bfloat16 *xq, *xkv, *wqe, *wke, *wve, *woe, *q, *k, *v, *ao;
    cudaGetSymbolAddress((void**)&xq,  g_Xq);
    cudaGetSymbolAddress((void**)&xkv, g_Xkv);
    cudaGetSymbolAddress((void**)&wqe, g_Wq);
    cudaGetSymbolAddress((void**)&wke, g_Wk);
    cudaGetSymbolAddress((void**)&wve, g_Wv);
    cudaGetSymbolAddress((void**)&woe, g_Wo);
    cudaGetSymbolAddress((void**)&q,   g_Q);
    cudaGetSymbolAddress((void**)&k,   g_K);
    cudaGetSymbolAddress((void**)&v,   g_V);
    cudaGetSymbolAddress((void**)&ao,  g_AO);

    // opt-in dynamic SMEM (idempotent host calls)
    const int SMEM_A = 3 * AQ_BYTES + 3072;       // 107520
    const int SMEM_B = 4 * AQ_BYTES + 1024;       // 140288
    cudaFuncSetAttribute(k_gemm_mma,       cudaFuncAttributeMaxDynamicSharedMemorySize, GSMEM);
    cudaFuncSetAttribute(k_attn_stats_mma, cudaFuncAttributeMaxDynamicSharedMemorySize, SMEM_A);
    cudaFuncSetAttribute(k_attn_av_mma,    cudaFuncAttributeMaxDynamicSharedMemorySize, SMEM_B);

    // quantize activations; transpose+quantize weights (mma B operand is [N,K])
    k_quant_f32<<<NACT / 256, 256>>>(in_q,  xq,  NACT);
    k_quant_f32<<<NACT / 256, 256>>>(in_kv, xkv, NACT);
    dim3 gt(DMODEL / 32, DMODEL / 32);
    k_wtrans<<<gt, 1024>>>(wq, wqe);
    k_wtrans<<<gt, 1024>>>(wk, wke);
    k_wtrans<<<gt, 1024>>>(wv, wve);
    k_wtrans<<<gt, 1024>>>(wo, woe);

    // projections on tensor cores (V fuses e4m3 re-quant into epilogue)
    dim3 gg(DMODEL / TBN, MROWS / TBM);
    k_gemm_mma<<<gg, 256, GSMEM>>>(xq,  wqe, q, MROWS, DMODEL, DMODEL, 0);
    k_gemm_mma<<<gg, 256, GSMEM>>>(xkv, wke, k, MROWS, DMODEL, DMODEL, 0);
    k_gemm_mma<<<gg, 256, GSMEM>>>(xkv, wve, v, MROWS, DMODEL, DMODEL, 1);

    // attention on tensor cores: stats pass then AV pass (cp.async pipelined)
    dim3 ga(SEQ / 128, BATCH * NHEAD);
    k_attn_stats_mma<<<ga, 256, SMEM_A>>>();
    k_attn_av_mma<<<ga, 256, SMEM_B>>>();

    // output projection: bf16-rounded values widened to FLOAT32 output buffer
    k_gemm_mma<<<gg, 256, GSMEM>>>(ao, woe, d_out, MROWS, DMODEL, DMODEL, 2);
}